// round 11
// baseline (speedup 1.0000x reference)
#include <cuda_runtime.h>
#include <cuda_fp16.h>
#include <stdint.h>
#include <math.h>

#define EPSV 1e-5f
#define BB   2
#define CIN  64
#define COUT 64
#define HH_  64
#define WW_  2048
#define NPIX (HH_ * WW_)      // 131072
#define BN   (BB * NPIX)      // 262144

// Softmax gate scratch: s[k][b*NPIX + n], 9 coalesced planes (9.4 MB)
__device__ float g_s[9 * BN];
// Pre-swizzled fp16 Wagg tiles: per k-chunk, 64 rows (o) x 128B (64 c fp16)
__device__ __align__(16) unsigned char g_Bhi[9][8192];

#define SW128(b) ((b) ^ (((b) >> 3) & 0x70))

static __device__ __forceinline__ uint32_t smem_u32(const void* p) {
    uint32_t a;
    asm("{ .reg .u64 t; cvta.to.shared.u64 t, %1; cvt.u32.u64 %0, t; }"
        : "=r"(a) : "l"(p));
    return a;
}

static __device__ __forceinline__ void ldsm4(uint32_t addr, uint32_t* r) {
    asm volatile("ldmatrix.sync.aligned.m8n8.x4.shared.b16 {%0,%1,%2,%3}, [%4];"
                 : "=r"(r[0]), "=r"(r[1]), "=r"(r[2]), "=r"(r[3]) : "r"(addr));
}

static __device__ __forceinline__ void hmma(float* c, const uint32_t* a, const uint32_t* b) {
    asm volatile("mma.sync.aligned.m16n8k16.row.col.f32.f16.f16.f32 "
                 "{%0,%1,%2,%3}, {%4,%5,%6,%7}, {%8,%9}, {%0,%1,%2,%3};"
                 : "+f"(c[0]), "+f"(c[1]), "+f"(c[2]), "+f"(c[3])
                 : "r"(a[0]), "r"(a[1]), "r"(a[2]), "r"(a[3]), "r"(b[0]), "r"(b[1]));
}

// ---------------------------------------------------------------------------
// Phase 1: per-pixel 9-way softmax gates (unchanged).
// ---------------------------------------------------------------------------
__global__ __launch_bounds__(256) void phase1_gates(
    const float* __restrict__ x, const int* __restrict__ mask,
    const float* __restrict__ W1, const float* __restrict__ g1,
    const float* __restrict__ b1, const float* __restrict__ m1,
    const float* __restrict__ v1, const float* __restrict__ W2,
    const float* __restrict__ b2)
{
    __shared__ float4 sW1[CIN];
    __shared__ float2 sBW[CIN];

    int tid = threadIdx.x;
    if (tid < CIN) {
        float a = g1[tid] * rsqrtf(v1[tid] + EPSV);
        sW1[tid] = make_float4(W1[tid * 4 + 0] * a, W1[tid * 4 + 1] * a,
                               W1[tid * 4 + 2] * a, W1[tid * 4 + 3] * a);
        sBW[tid] = make_float2(b1[tid] - m1[tid] * a, W2[tid]);
    }
    __syncthreads();

    int g = blockIdx.x * 256 + tid;
    int b = g / NPIX;
    int n = g - b * NPIX;
    int h = n / WW_;
    int w = n - h * WW_;

    const float* xb = x + (size_t)b * (CIN + 4) * NPIX;
    const int*   mb = mask + (size_t)b * NPIX;

    float c0 = xb[0 * NPIX + n];
    float c1 = xb[1 * NPIX + n];
    float c2 = xb[2 * NPIX + n];
    float c3 = xb[3 * NPIX + n];

    float d0[9], d1[9], d2[9], d3[9];
    bool  act[9];
#pragma unroll
    for (int k = 0; k < 9; ++k) {
        int kh = k / 3 - 1, kw = k % 3 - 1;
        int hh = h + kh, ww = w + kw;
        bool valid = (hh >= 0) && (hh < HH_) && (ww >= 0) && (ww < WW_);
        int nn = valid ? (hh * WW_ + ww) : n;
        act[k] = valid && (mb[nn] != 0);
        d0[k] = xb[0 * NPIX + nn] - c0;
        d1[k] = xb[1 * NPIX + nn] - c1;
        d2[k] = xb[2 * NPIX + nn] - c2;
        d3[k] = xb[3 * NPIX + nn] - c3;
    }

    float b2v = __ldg(b2);
    float lg[9];
#pragma unroll
    for (int k = 0; k < 9; ++k) lg[k] = b2v;

    for (int c = 0; c < CIN; ++c) {
        float4 wv = sW1[c];
        float2 bw = sBW[c];
#pragma unroll
        for (int k = 0; k < 9; ++k) {
            float t = fmaf(d0[k], wv.x,
                      fmaf(d1[k], wv.y,
                      fmaf(d2[k], wv.z,
                      fmaf(d3[k], wv.w, bw.x))));
            t = fmaxf(t, 0.0f);
            lg[k] = fmaf(t, bw.y, lg[k]);
        }
    }

#pragma unroll
    for (int k = 0; k < 9; ++k) lg[k] = act[k] ? lg[k] : 0.0f;

    float mx = lg[0];
#pragma unroll
    for (int k = 1; k < 9; ++k) mx = fmaxf(mx, lg[k]);
    float e[9], sum = 0.0f;
#pragma unroll
    for (int k = 0; k < 9; ++k) { e[k] = __expf(lg[k] - mx); sum += e[k]; }
    float inv = __frcp_rn(sum);
#pragma unroll
    for (int k = 0; k < 9; ++k) g_s[k * BN + g] = e[k] * inv;
}

// ---------------------------------------------------------------------------
// Prep: Wagg -> fp16 SW128-swizzled smem image per k-chunk.
// ---------------------------------------------------------------------------
__global__ void prep_B(const float* __restrict__ Wagg)
{
    int kc = blockIdx.x;      // 0..575
    int o  = threadIdx.x;     // 0..63
    int k = kc >> 6, c = kc & 63;
    float w = Wagg[(size_t)o * 576 + kc];
    uint32_t off = SW128((uint32_t)(o * 128 + c * 2));
    *(__half*)(g_Bhi[k] + off) = __float2half_rn(w);
}

// ---------------------------------------------------------------------------
// Phase 2: feature-resident HMMA GEMM, 2 CTAs/SM for prologue/mainloop overlap.
// CTA = 128 px x 32 out, 128 threads (4 warps, each 32px x 32out).
// smem: feat 3 planes x 130 px-rows x 128B (SW128, 1KB-aligned planes)
//       | B-half [9][4KB] | gates fp32[9][128]  = 93.7KB -> 2 CTAs/SM.
// blockIdx.x = (wtile<<1)|ohalf: adjacent CTAs share the feat tile (L2 hot).
// ---------------------------------------------------------------------------
#define PLANE   17408                    // 130*128 padded to 1KB multiple
#define SM_FEAT 0
#define SM_BW   (3 * PLANE)              // 52224
#define SM_SG   (SM_BW + 9 * 4096)       // 89088
#define SM_TOTAL (SM_SG + 9 * 128 * 4)   // 93696

__global__ __launch_bounds__(128, 2) void phase2_hmma(
    const float* __restrict__ x,
    const float* __restrict__ g2, const float* __restrict__ b2g,
    const float* __restrict__ m2, const float* __restrict__ v2,
    float* __restrict__ y)
{
    extern __shared__ char sm[];
    int tid  = threadIdx.x;
    int lane = tid & 31;
    int wid  = tid >> 5;
    int b    = blockIdx.z;
    int h    = blockIdx.y;
    int half = blockIdx.x & 1;
    int w0   = (blockIdx.x >> 1) * 128;
    int obase = half * 32;

    uint32_t smb = smem_u32(sm);
    int pbase = wid * 32;          // 4 m-tiles of 32 px

    // ---- copy B half-chunks: rows [obase, obase+32) of each k, verbatim ----
    // (SW128 permutes only bits [4:7) so a 4KB half-chunk is a valid image)
    {
        uint4* dstB = (uint4*)(sm + SM_BW);
#pragma unroll
        for (int k = 0; k < 9; ++k) {
            const uint4* srcB = (const uint4*)(g_Bhi[k] + half * 4096);
            dstB[k * 256 + tid]       = srcB[tid];
            dstB[k * 256 + tid + 128] = srcB[tid + 128];
        }
    }

    // ---- gates fp32 [k][p] ----
    float* sg = (float*)(sm + SM_SG);
    {
        size_t gb = (size_t)b * NPIX + (size_t)h * WW_ + w0;
#pragma unroll
        for (int i = 0; i < 9; ++i) {
            int j = tid + 128 * i;
            sg[j] = g_s[(size_t)(j >> 7) * BN + gb + (j & 127)];
        }
    }

    // ---- feature tile: 3 planes x 130 px-rows x 64c fp16, SW128 ----
    const float* xf = x + ((size_t)b * (CIN + 4) + 4) * NPIX;
    {
        int p = tid;               // main region: pixel w0+p -> q row p+1
#pragma unroll
        for (int r = 0; r < 3; ++r) {
            int hh = h + r - 1;
            bool hv = (hh >= 0) && (hh < HH_);
            const float* rowp = xf + (size_t)hh * WW_ + w0 + p;
            char* plane = sm + SM_FEAT + r * PLANE;
            uint32_t qb = (uint32_t)((p + 1) * 128);
#pragma unroll 8
            for (int c2 = 0; c2 < 32; ++c2) {
                int c = 2 * c2;
                float f0 = hv ? __ldg(rowp + (size_t)c       * NPIX) : 0.0f;
                float f1 = hv ? __ldg(rowp + (size_t)(c + 1) * NPIX) : 0.0f;
                __half2 v = __floats2half2_rn(f0, f1);
                *(uint32_t*)(plane + SW128(qb + (uint32_t)(c * 2))) = *(uint32_t*)&v;
            }
        }
        // halo columns: q=0 (w0-1) and q=129 (w0+128); 2x3x32 = 192 c-pair tasks
#pragma unroll
        for (int t = 0; t < 2; ++t) {
            int i = tid + t * 128;
            if (i < 192) {
                int r    = i / 64;
                int qsel = (i & 63) >> 5;
                int cc   = (i & 31) * 2;
                int q    = qsel ? 129 : 0;
                int wg   = w0 + (qsel ? 128 : -1);
                int hh   = h + r - 1;
                bool v_  = (hh >= 0) && (hh < HH_) && (wg >= 0) && (wg < WW_);
                const float* rowp = xf + (size_t)hh * WW_ + wg;
                float f0 = v_ ? __ldg(rowp + (size_t)cc       * NPIX) : 0.0f;
                float f1 = v_ ? __ldg(rowp + (size_t)(cc + 1) * NPIX) : 0.0f;
                __half2 vv = __floats2half2_rn(f0, f1);
                *(uint32_t*)(sm + SM_FEAT + r * PLANE +
                             SW128((uint32_t)(q * 128 + cc * 2))) = *(uint32_t*)&vv;
            }
        }
    }
    __syncthreads();

    // ---- fragment addressing ----
    uint32_t aq   = (uint32_t)(pbase + (lane & 15));
    uint32_t acol = (uint32_t)((lane >> 4) * 16);
    uint32_t bg   = (uint32_t)(lane >> 3);
    uint32_t b_n  = (uint32_t)(((bg >> 1) << 3) + (lane & 7));  // local 0..15
    uint32_t b_kb = (bg & 1) * 16;
    int srow = pbase + (lane >> 2);

    float acc[2][4][4];
#pragma unroll
    for (int mt = 0; mt < 2; ++mt)
#pragma unroll
        for (int nt = 0; nt < 4; ++nt)
#pragma unroll
            for (int j = 0; j < 4; ++j) acc[mt][nt][j] = 0.0f;

#pragma unroll
    for (int k = 0; k < 9; ++k) {
        uint32_t pl    = smb + SM_FEAT + (uint32_t)((k / 3) * PLANE);
        uint32_t qoff  = (uint32_t)(k % 3);
        uint32_t bbase = smb + SM_BW + (uint32_t)(k * 4096);

        float tmp[2][4][4];
#pragma unroll
        for (int mt = 0; mt < 2; ++mt)
#pragma unroll
            for (int nt = 0; nt < 4; ++nt)
#pragma unroll
                for (int j = 0; j < 4; ++j) tmp[mt][nt][j] = 0.0f;

#pragma unroll
        for (int ks = 0; ks < 4; ++ks) {
            uint32_t ah[2][4], bh[2][4];
#pragma unroll
            for (int mt = 0; mt < 2; ++mt) {
                uint32_t off = SW128((aq + qoff + mt * 16) * 128 +
                                     (uint32_t)(ks * 32) + acol);
                ldsm4(pl + off, ah[mt]);
            }
#pragma unroll
            for (int nt2 = 0; nt2 < 2; ++nt2) {
                uint32_t off = SW128((b_n + nt2 * 16) * 128 +
                                     (uint32_t)(ks * 32) + b_kb);
                ldsm4(bbase + off, bh[nt2]);
            }
#pragma unroll
            for (int mt = 0; mt < 2; ++mt)
#pragma unroll
                for (int nt = 0; nt < 4; ++nt)
                    hmma(tmp[mt][nt], ah[mt], &bh[nt >> 1][(nt & 1) * 2]);
        }

        // fold with fp32 gates
#pragma unroll
        for (int mt = 0; mt < 2; ++mt) {
            float s_a = sg[k * 128 + srow + mt * 16];
            float s_b = sg[k * 128 + srow + mt * 16 + 8];
#pragma unroll
            for (int nt = 0; nt < 4; ++nt) {
                acc[mt][nt][0] = fmaf(s_a, tmp[mt][nt][0], acc[mt][nt][0]);
                acc[mt][nt][1] = fmaf(s_a, tmp[mt][nt][1], acc[mt][nt][1]);
                acc[mt][nt][2] = fmaf(s_b, tmp[mt][nt][2], acc[mt][nt][2]);
                acc[mt][nt][3] = fmaf(s_b, tmp[mt][nt][3], acc[mt][nt][3]);
            }
        }
    }

    // ---- epilogue: BN2 + ReLU + store (32 outputs of this half) ----
    __syncthreads();
    float* sc = (float*)sm;
    float* sh = sc + 32;
    if (tid < 32) {
        int o = obase + tid;
        float a2 = g2[o] * rsqrtf(v2[o] + EPSV);
        sc[tid] = a2;
        sh[tid] = b2g[o] - m2[o] * a2;
    }
    __syncthreads();

    float* yb = y + ((size_t)b * COUT + obase) * NPIX + (size_t)h * WW_ + w0;
    int rbase = pbase + (lane >> 2);
    int cbase = (lane & 3) * 2;
#pragma unroll
    for (int mt = 0; mt < 2; ++mt) {
#pragma unroll
        for (int nt = 0; nt < 4; ++nt) {
            int o0 = cbase + nt * 8;             // local 0..31
            int r0 = rbase + mt * 16;
            float s0 = sc[o0], h0 = sh[o0];
            float s1 = sc[o0 + 1], h1 = sh[o0 + 1];
            yb[(size_t)o0       * NPIX + r0]     = fmaxf(fmaf(acc[mt][nt][0], s0, h0), 0.0f);
            yb[(size_t)(o0 + 1) * NPIX + r0]     = fmaxf(fmaf(acc[mt][nt][1], s1, h1), 0.0f);
            yb[(size_t)o0       * NPIX + r0 + 8] = fmaxf(fmaf(acc[mt][nt][2], s0, h0), 0.0f);
            yb[(size_t)(o0 + 1) * NPIX + r0 + 8] = fmaxf(fmaf(acc[mt][nt][3], s1, h1), 0.0f);
        }
    }
}

// ---------------------------------------------------------------------------
extern "C" void kernel_launch(void* const* d_in, const int* in_sizes, int n_in,
                              void* d_out, int out_size)
{
    const float* x     = (const float*)d_in[0];
    const int*   mask  = (const int*)  d_in[1];
    const float* W1    = (const float*)d_in[2];
    const float* bn1_g = (const float*)d_in[3];
    const float* bn1_b = (const float*)d_in[4];
    const float* bn1_m = (const float*)d_in[5];
    const float* bn1_v = (const float*)d_in[6];
    const float* W2    = (const float*)d_in[7];
    const float* b2    = (const float*)d_in[8];
    const float* Wagg  = (const float*)d_in[9];
    const float* bn2_g = (const float*)d_in[10];
    const float* bn2_b = (const float*)d_in[11];
    const float* bn2_m = (const float*)d_in[12];
    const float* bn2_v = (const float*)d_in[13];
    float* y = (float*)d_out;

    static int smem_set = 0;
    if (!smem_set) {
        cudaFuncSetAttribute(phase2_hmma, cudaFuncAttributeMaxDynamicSharedMemorySize,
                             SM_TOTAL);
        smem_set = 1;
    }

    prep_B<<<576, 64>>>(Wagg);
    phase1_gates<<<BN / 256, 256>>>(x, mask, W1, bn1_g, bn1_b, bn1_m, bn1_v, W2, b2);

    dim3 grid((WW_ / 128) * 2, HH_, BB);
    phase2_hmma<<<grid, 128, SM_TOTAL>>>(x, bn2_g, bn2_b, bn2_m, bn2_v, y);
}

// round 12
// speedup vs baseline: 1.3719x; 1.3719x over previous
#include <cuda_runtime.h>
#include <cuda_fp16.h>
#include <stdint.h>
#include <math.h>

#define EPSV 1e-5f
#define BB   2
#define CIN  64
#define COUT 64
#define HH_  64
#define WW_  2048
#define NPIX (HH_ * WW_)      // 131072
#define BN   (BB * NPIX)      // 262144
#define HCHUNK 8

// Softmax gate scratch: s[k][b*NPIX + n], 9 coalesced planes (9.4 MB)
__device__ float g_s[9 * BN];
// Pre-swizzled fp16 Wagg tiles: per k-chunk, 64 rows (o) x 128B (64 c fp16)
__device__ __align__(16) unsigned char g_Bhi[9][8192];

#define SW128(b) ((b) ^ (((b) >> 3) & 0x70))

static __device__ __forceinline__ uint32_t smem_u32(const void* p) {
    uint32_t a;
    asm("{ .reg .u64 t; cvta.to.shared.u64 t, %1; cvt.u32.u64 %0, t; }"
        : "=r"(a) : "l"(p));
    return a;
}

static __device__ __forceinline__ void ldsm4(uint32_t addr, uint32_t* r) {
    asm volatile("ldmatrix.sync.aligned.m8n8.x4.shared.b16 {%0,%1,%2,%3}, [%4];"
                 : "=r"(r[0]), "=r"(r[1]), "=r"(r[2]), "=r"(r[3]) : "r"(addr));
}

static __device__ __forceinline__ void hmma(float* c, const uint32_t* a, const uint32_t* b) {
    asm volatile("mma.sync.aligned.m16n8k16.row.col.f32.f16.f16.f32 "
                 "{%0,%1,%2,%3}, {%4,%5,%6,%7}, {%8,%9}, {%0,%1,%2,%3};"
                 : "+f"(c[0]), "+f"(c[1]), "+f"(c[2]), "+f"(c[3])
                 : "r"(a[0]), "r"(a[1]), "r"(a[2]), "r"(a[3]), "r"(b[0]), "r"(b[1]));
}

// ---------------------------------------------------------------------------
// Phase 1: per-pixel 9-way softmax gates (unchanged).
// ---------------------------------------------------------------------------
__global__ __launch_bounds__(256) void phase1_gates(
    const float* __restrict__ x, const int* __restrict__ mask,
    const float* __restrict__ W1, const float* __restrict__ g1,
    const float* __restrict__ b1, const float* __restrict__ m1,
    const float* __restrict__ v1, const float* __restrict__ W2,
    const float* __restrict__ b2)
{
    __shared__ float4 sW1[CIN];
    __shared__ float2 sBW[CIN];

    int tid = threadIdx.x;
    if (tid < CIN) {
        float a = g1[tid] * rsqrtf(v1[tid] + EPSV);
        sW1[tid] = make_float4(W1[tid * 4 + 0] * a, W1[tid * 4 + 1] * a,
                               W1[tid * 4 + 2] * a, W1[tid * 4 + 3] * a);
        sBW[tid] = make_float2(b1[tid] - m1[tid] * a, W2[tid]);
    }
    __syncthreads();

    int g = blockIdx.x * 256 + tid;
    int b = g / NPIX;
    int n = g - b * NPIX;
    int h = n / WW_;
    int w = n - h * WW_;

    const float* xb = x + (size_t)b * (CIN + 4) * NPIX;
    const int*   mb = mask + (size_t)b * NPIX;

    float c0 = xb[0 * NPIX + n];
    float c1 = xb[1 * NPIX + n];
    float c2 = xb[2 * NPIX + n];
    float c3 = xb[3 * NPIX + n];

    float d0[9], d1[9], d2[9], d3[9];
    bool  act[9];
#pragma unroll
    for (int k = 0; k < 9; ++k) {
        int kh = k / 3 - 1, kw = k % 3 - 1;
        int hh = h + kh, ww = w + kw;
        bool valid = (hh >= 0) && (hh < HH_) && (ww >= 0) && (ww < WW_);
        int nn = valid ? (hh * WW_ + ww) : n;
        act[k] = valid && (mb[nn] != 0);
        d0[k] = xb[0 * NPIX + nn] - c0;
        d1[k] = xb[1 * NPIX + nn] - c1;
        d2[k] = xb[2 * NPIX + nn] - c2;
        d3[k] = xb[3 * NPIX + nn] - c3;
    }

    float b2v = __ldg(b2);
    float lg[9];
#pragma unroll
    for (int k = 0; k < 9; ++k) lg[k] = b2v;

    for (int c = 0; c < CIN; ++c) {
        float4 wv = sW1[c];
        float2 bw = sBW[c];
#pragma unroll
        for (int k = 0; k < 9; ++k) {
            float t = fmaf(d0[k], wv.x,
                      fmaf(d1[k], wv.y,
                      fmaf(d2[k], wv.z,
                      fmaf(d3[k], wv.w, bw.x))));
            t = fmaxf(t, 0.0f);
            lg[k] = fmaf(t, bw.y, lg[k]);
        }
    }

#pragma unroll
    for (int k = 0; k < 9; ++k) lg[k] = act[k] ? lg[k] : 0.0f;

    float mx = lg[0];
#pragma unroll
    for (int k = 1; k < 9; ++k) mx = fmaxf(mx, lg[k]);
    float e[9], sum = 0.0f;
#pragma unroll
    for (int k = 0; k < 9; ++k) { e[k] = __expf(lg[k] - mx); sum += e[k]; }
    float inv = __frcp_rn(sum);
#pragma unroll
    for (int k = 0; k < 9; ++k) g_s[k * BN + g] = e[k] * inv;
}

// ---------------------------------------------------------------------------
// Prep: Wagg -> fp16 SW128-swizzled smem image per k-chunk.
// ---------------------------------------------------------------------------
__global__ void prep_B(const float* __restrict__ Wagg)
{
    int kc = blockIdx.x;      // 0..575
    int o  = threadIdx.x;     // 0..63
    int k = kc >> 6, c = kc & 63;
    float w = Wagg[(size_t)o * 576 + kc];
    uint32_t off = SW128((uint32_t)(o * 128 + c * 2));
    *(__half*)(g_Bhi[k] + off) = __float2half_rn(w);
}

// ---------------------------------------------------------------------------
// Phase 2: persistent h-chunk HMMA GEMM with rolling feature-plane ring.
// CTA = 256 px x 64 out x 8 h-rows. 512 threads (16 warps: 8m x 2n).
// smem: plane ring[4] x 33KB | B[9][8KB] | gates[2][9][256] | BN consts.
// Per h-iter: prefetch next plane + next gates, mainloop (no smem hazard),
// epilogue, one __syncthreads.
// ---------------------------------------------------------------------------
#define PLANE   33792                       // 258*128 padded
#define SM_FEAT 0
#define SM_BW   (4 * PLANE)                 // 135168
#define SM_SG   (SM_BW + 9 * 8192)          // 208896
#define SM_BN   (SM_SG + 2 * 9 * 256 * 4)   // 227328
#define SM_TOTAL (SM_BN + 512)              // 227840

static __device__ __forceinline__ void load_plane(
    char* sm, int slot, int hh, int w0, const float* __restrict__ xf, int tid)
{
    char* plane = sm + SM_FEAT + slot * PLANE;
    bool hv = (hh >= 0) && (hh < HH_);
    int p   = tid & 255;
    int ch0 = (tid >> 8) * 32;
    const float* rowp = xf + (size_t)hh * WW_ + w0 + p;
    uint32_t qb = (uint32_t)((p + 1) * 128);
#pragma unroll 4
    for (int c2 = 0; c2 < 16; ++c2) {
        int c = ch0 + 2 * c2;
        float f0 = hv ? __ldg(rowp + (size_t)c       * NPIX) : 0.0f;
        float f1 = hv ? __ldg(rowp + (size_t)(c + 1) * NPIX) : 0.0f;
        __half2 v = __floats2half2_rn(f0, f1);
        *(uint32_t*)(plane + SW128(qb + (uint32_t)(c * 2))) = *(uint32_t*)&v;
    }
    // halo: q=0 (w0-1), q=257 (w0+256); 2 x 32 c-pairs
    if (tid < 64) {
        int qsel = tid >> 5;
        int cc   = (tid & 31) * 2;
        int q    = qsel ? 257 : 0;
        int wg   = w0 + (qsel ? 256 : -1);
        bool v_  = hv && (wg >= 0) && (wg < WW_);
        const float* rp = xf + (size_t)hh * WW_ + wg;
        float f0 = v_ ? __ldg(rp + (size_t)cc       * NPIX) : 0.0f;
        float f1 = v_ ? __ldg(rp + (size_t)(cc + 1) * NPIX) : 0.0f;
        __half2 vv = __floats2half2_rn(f0, f1);
        *(uint32_t*)(plane + SW128((uint32_t)(q * 128 + cc * 2))) = *(uint32_t*)&vv;
    }
}

static __device__ __forceinline__ void load_gates(
    float* dst, int b, int h, int w0, int tid)
{
    size_t gb = (size_t)b * NPIX + (size_t)h * WW_ + w0;
#pragma unroll
    for (int i = 0; i < 5; ++i) {
        int j = tid + 512 * i;
        if (j < 2304)
            dst[j] = g_s[(size_t)(j >> 8) * BN + gb + (j & 255)];
    }
}

__global__ __launch_bounds__(512, 1) void phase2_hmma(
    const float* __restrict__ x,
    const float* __restrict__ g2, const float* __restrict__ b2g,
    const float* __restrict__ m2, const float* __restrict__ v2,
    float* __restrict__ y)
{
    extern __shared__ char sm[];
    int tid  = threadIdx.x;
    int lane = tid & 31;
    int wid  = tid >> 5;
    int b  = blockIdx.z;
    int h0 = blockIdx.y * HCHUNK;
    int w0 = blockIdx.x * 256;

    uint32_t smb = smem_u32(sm);

    int warp_m = wid & 7;          // 8 m-tiles of 32 px
    int warp_n = wid >> 3;         // 2 n-tiles of 32 out
    int pbase  = warp_m * 32;
    int obase  = warp_n * 32;

    const float* xf = x + ((size_t)b * (CIN + 4) + 4) * NPIX;

    // ---- prologue: B (72KB), BN consts, gates(h0), planes h0-1,h0,h0+1 ----
    {
        const uint4* srcB = (const uint4*)g_Bhi;
        uint4* dstB = (uint4*)(sm + SM_BW);
#pragma unroll
        for (int i = 0; i < 9; ++i)
            dstB[tid + 512 * i] = srcB[tid + 512 * i];
    }
    {
        float* sc = (float*)(sm + SM_BN);
        float* sh = sc + 64;
        if (tid < 64) {
            float a2 = g2[tid] * rsqrtf(v2[tid] + EPSV);
            sc[tid] = a2;
            sh[tid] = b2g[tid] - m2[tid] * a2;
        }
    }
    load_gates((float*)(sm + SM_SG), b, h0, w0, tid);
    load_plane(sm, 0, h0 - 1, w0, xf, tid);
    load_plane(sm, 1, h0,     w0, xf, tid);
    load_plane(sm, 2, h0 + 1, w0, xf, tid);
    __syncthreads();

    // ---- fragment addressing ----
    uint32_t aq   = (uint32_t)(pbase + (lane & 15));
    uint32_t acol = (uint32_t)((lane >> 4) * 16);
    uint32_t bg   = (uint32_t)(lane >> 3);
    uint32_t b_n  = (uint32_t)(obase + ((bg >> 1) << 3) + (lane & 7));
    uint32_t b_kb = (bg & 1) * 16;
    int srow = pbase + (lane >> 2);

    const float* sc = (const float*)(sm + SM_BN);
    const float* sh = sc + 64;
    int rbase = pbase + (lane >> 2);
    int cbase = obase + (lane & 3) * 2;

    for (int i = 0; i < HCHUNK; ++i) {
        int h = h0 + i;

        // ---- prefetch next plane + next gates (writes slot (i+3)&3, buf (i+1)&1;
        //      current mainloop reads slots i..i+2 (&3) and buf i&1) ----
        if (i < HCHUNK - 1) {
            load_plane(sm, (i + 3) & 3, h + 2, w0, xf, tid);
            load_gates((float*)(sm + SM_SG) + ((i + 1) & 1) * 2304, b, h + 1, w0, tid);
        }

        const float* sg = (const float*)(sm + SM_SG) + (i & 1) * 2304;

        float acc[2][4][4];
#pragma unroll
        for (int mt = 0; mt < 2; ++mt)
#pragma unroll
            for (int nt = 0; nt < 4; ++nt)
#pragma unroll
                for (int j = 0; j < 4; ++j) acc[mt][nt][j] = 0.0f;

#pragma unroll
        for (int k = 0; k < 9; ++k) {
            uint32_t pl    = smb + SM_FEAT + (uint32_t)(((i + k / 3) & 3) * PLANE);
            uint32_t qoff  = (uint32_t)(k % 3);
            uint32_t bbase = smb + SM_BW + (uint32_t)(k * 8192);

            float tmp[2][4][4];
#pragma unroll
            for (int mt = 0; mt < 2; ++mt)
#pragma unroll
                for (int nt = 0; nt < 4; ++nt)
#pragma unroll
                    for (int j = 0; j < 4; ++j) tmp[mt][nt][j] = 0.0f;

#pragma unroll
            for (int ks = 0; ks < 4; ++ks) {
                uint32_t ah[2][4], bh[2][4];
#pragma unroll
                for (int mt = 0; mt < 2; ++mt) {
                    uint32_t off = SW128((aq + qoff + mt * 16) * 128 +
                                         (uint32_t)(ks * 32) + acol);
                    ldsm4(pl + off, ah[mt]);
                }
#pragma unroll
                for (int nt2 = 0; nt2 < 2; ++nt2) {
                    uint32_t off = SW128((b_n + nt2 * 16) * 128 +
                                         (uint32_t)(ks * 32) + b_kb);
                    ldsm4(bbase + off, bh[nt2]);
                }
#pragma unroll
                for (int mt = 0; mt < 2; ++mt)
#pragma unroll
                    for (int nt = 0; nt < 4; ++nt)
                        hmma(tmp[mt][nt], ah[mt], &bh[nt >> 1][(nt & 1) * 2]);
            }

#pragma unroll
            for (int mt = 0; mt < 2; ++mt) {
                float s_a = sg[k * 256 + srow + mt * 16];
                float s_b = sg[k * 256 + srow + mt * 16 + 8];
#pragma unroll
                for (int nt = 0; nt < 4; ++nt) {
                    acc[mt][nt][0] = fmaf(s_a, tmp[mt][nt][0], acc[mt][nt][0]);
                    acc[mt][nt][1] = fmaf(s_a, tmp[mt][nt][1], acc[mt][nt][1]);
                    acc[mt][nt][2] = fmaf(s_b, tmp[mt][nt][2], acc[mt][nt][2]);
                    acc[mt][nt][3] = fmaf(s_b, tmp[mt][nt][3], acc[mt][nt][3]);
                }
            }
        }

        // ---- epilogue for row h: BN2 + ReLU + store ----
        float* yb = y + ((size_t)b * COUT) * NPIX + (size_t)h * WW_ + w0;
#pragma unroll
        for (int mt = 0; mt < 2; ++mt) {
#pragma unroll
            for (int nt = 0; nt < 4; ++nt) {
                int o0 = cbase + nt * 8;
                int r0 = rbase + mt * 16;
                float s0 = sc[o0], h0c = sh[o0];
                float s1 = sc[o0 + 1], h1c = sh[o0 + 1];
                yb[(size_t)o0       * NPIX + r0]     = fmaxf(fmaf(acc[mt][nt][0], s0, h0c), 0.0f);
                yb[(size_t)(o0 + 1) * NPIX + r0]     = fmaxf(fmaf(acc[mt][nt][1], s1, h1c), 0.0f);
                yb[(size_t)o0       * NPIX + r0 + 8] = fmaxf(fmaf(acc[mt][nt][2], s0, h0c), 0.0f);
                yb[(size_t)(o0 + 1) * NPIX + r0 + 8] = fmaxf(fmaf(acc[mt][nt][3], s1, h1c), 0.0f);
            }
        }

        __syncthreads();
    }
}

// ---------------------------------------------------------------------------
extern "C" void kernel_launch(void* const* d_in, const int* in_sizes, int n_in,
                              void* d_out, int out_size)
{
    const float* x     = (const float*)d_in[0];
    const int*   mask  = (const int*)  d_in[1];
    const float* W1    = (const float*)d_in[2];
    const float* bn1_g = (const float*)d_in[3];
    const float* bn1_b = (const float*)d_in[4];
    const float* bn1_m = (const float*)d_in[5];
    const float* bn1_v = (const float*)d_in[6];
    const float* W2    = (const float*)d_in[7];
    const float* b2    = (const float*)d_in[8];
    const float* Wagg  = (const float*)d_in[9];
    const float* bn2_g = (const float*)d_in[10];
    const float* bn2_b = (const float*)d_in[11];
    const float* bn2_m = (const float*)d_in[12];
    const float* bn2_v = (const float*)d_in[13];
    float* y = (float*)d_out;

    static int smem_set = 0;
    if (!smem_set) {
        cudaFuncSetAttribute(phase2_hmma, cudaFuncAttributeMaxDynamicSharedMemorySize,
                             SM_TOTAL);
        smem_set = 1;
    }

    prep_B<<<576, 64>>>(Wagg);
    phase1_gates<<<BN / 256, 256>>>(x, mask, W1, bn1_g, bn1_b, bn1_m, bn1_v, W2, b2);

    dim3 grid(WW_ / 256, HH_ / HCHUNK, BB);
    phase2_hmma<<<grid, 512, SM_TOTAL>>>(x, bn2_g, bn2_b, bn2_m, bn2_v, y);
}

// round 13
// speedup vs baseline: 1.4662x; 1.0687x over previous
#include <cuda_runtime.h>
#include <cuda_fp16.h>
#include <stdint.h>
#include <math.h>

#define EPSV 1e-5f
#define BB   2
#define CIN  64
#define COUT 64
#define HH_  64
#define WW_  2048
#define NPIX (HH_ * WW_)      // 131072
#define BN   (BB * NPIX)      // 262144
#define HCHUNK 8

// Softmax gate scratch: s[k][b*NPIX + n], 9 coalesced planes (9.4 MB)
__device__ float g_s[9 * BN];
// Pre-swizzled fp16 Wagg tiles: per k-chunk, 64 rows (o) x 128B (64 c fp16)
__device__ __align__(16) unsigned char g_Bhi[9][8192];

#define SW128(b) ((b) ^ (((b) >> 3) & 0x70))

static __device__ __forceinline__ uint32_t smem_u32(const void* p) {
    uint32_t a;
    asm("{ .reg .u64 t; cvta.to.shared.u64 t, %1; cvt.u32.u64 %0, t; }"
        : "=r"(a) : "l"(p));
    return a;
}

static __device__ __forceinline__ void cp_async16(uint32_t saddr, const void* gptr) {
    asm volatile("cp.async.ca.shared.global [%0], [%1], 16;"
                 :: "r"(saddr), "l"(gptr) : "memory");
}

static __device__ __forceinline__ void ldsm4(uint32_t addr, uint32_t* r) {
    asm volatile("ldmatrix.sync.aligned.m8n8.x4.shared.b16 {%0,%1,%2,%3}, [%4];"
                 : "=r"(r[0]), "=r"(r[1]), "=r"(r[2]), "=r"(r[3]) : "r"(addr));
}

static __device__ __forceinline__ void hmma(float* c, const uint32_t* a, const uint32_t* b) {
    asm volatile("mma.sync.aligned.m16n8k16.row.col.f32.f16.f16.f32 "
                 "{%0,%1,%2,%3}, {%4,%5,%6,%7}, {%8,%9}, {%0,%1,%2,%3};"
                 : "+f"(c[0]), "+f"(c[1]), "+f"(c[2]), "+f"(c[3])
                 : "r"(a[0]), "r"(a[1]), "r"(a[2]), "r"(a[3]), "r"(b[0]), "r"(b[1]));
}

// ---------------------------------------------------------------------------
// Phase 1: per-pixel 9-way softmax gates (unchanged).
// ---------------------------------------------------------------------------
__global__ __launch_bounds__(256) void phase1_gates(
    const float* __restrict__ x, const int* __restrict__ mask,
    const float* __restrict__ W1, const float* __restrict__ g1,
    const float* __restrict__ b1, const float* __restrict__ m1,
    const float* __restrict__ v1, const float* __restrict__ W2,
    const float* __restrict__ b2)
{
    __shared__ float4 sW1[CIN];
    __shared__ float2 sBW[CIN];

    int tid = threadIdx.x;
    if (tid < CIN) {
        float a = g1[tid] * rsqrtf(v1[tid] + EPSV);
        sW1[tid] = make_float4(W1[tid * 4 + 0] * a, W1[tid * 4 + 1] * a,
                               W1[tid * 4 + 2] * a, W1[tid * 4 + 3] * a);
        sBW[tid] = make_float2(b1[tid] - m1[tid] * a, W2[tid]);
    }
    __syncthreads();

    int g = blockIdx.x * 256 + tid;
    int b = g / NPIX;
    int n = g - b * NPIX;
    int h = n / WW_;
    int w = n - h * WW_;

    const float* xb = x + (size_t)b * (CIN + 4) * NPIX;
    const int*   mb = mask + (size_t)b * NPIX;

    float c0 = xb[0 * NPIX + n];
    float c1 = xb[1 * NPIX + n];
    float c2 = xb[2 * NPIX + n];
    float c3 = xb[3 * NPIX + n];

    float d0[9], d1[9], d2[9], d3[9];
    bool  act[9];
#pragma unroll
    for (int k = 0; k < 9; ++k) {
        int kh = k / 3 - 1, kw = k % 3 - 1;
        int hh = h + kh, ww = w + kw;
        bool valid = (hh >= 0) && (hh < HH_) && (ww >= 0) && (ww < WW_);
        int nn = valid ? (hh * WW_ + ww) : n;
        act[k] = valid && (mb[nn] != 0);
        d0[k] = xb[0 * NPIX + nn] - c0;
        d1[k] = xb[1 * NPIX + nn] - c1;
        d2[k] = xb[2 * NPIX + nn] - c2;
        d3[k] = xb[3 * NPIX + nn] - c3;
    }

    float b2v = __ldg(b2);
    float lg[9];
#pragma unroll
    for (int k = 0; k < 9; ++k) lg[k] = b2v;

    for (int c = 0; c < CIN; ++c) {
        float4 wv = sW1[c];
        float2 bw = sBW[c];
#pragma unroll
        for (int k = 0; k < 9; ++k) {
            float t = fmaf(d0[k], wv.x,
                      fmaf(d1[k], wv.y,
                      fmaf(d2[k], wv.z,
                      fmaf(d3[k], wv.w, bw.x))));
            t = fmaxf(t, 0.0f);
            lg[k] = fmaf(t, bw.y, lg[k]);
        }
    }

#pragma unroll
    for (int k = 0; k < 9; ++k) lg[k] = act[k] ? lg[k] : 0.0f;

    float mx = lg[0];
#pragma unroll
    for (int k = 1; k < 9; ++k) mx = fmaxf(mx, lg[k]);
    float e[9], sum = 0.0f;
#pragma unroll
    for (int k = 0; k < 9; ++k) { e[k] = __expf(lg[k] - mx); sum += e[k]; }
    float inv = __frcp_rn(sum);
#pragma unroll
    for (int k = 0; k < 9; ++k) g_s[k * BN + g] = e[k] * inv;
}

// ---------------------------------------------------------------------------
// Prep: Wagg -> fp16 SW128-swizzled smem image per k-chunk.
// ---------------------------------------------------------------------------
__global__ void prep_B(const float* __restrict__ Wagg)
{
    int kc = blockIdx.x;      // 0..575
    int o  = threadIdx.x;     // 0..63
    int k = kc >> 6, c = kc & 63;
    float w = Wagg[(size_t)o * 576 + kc];
    uint32_t off = SW128((uint32_t)(o * 128 + c * 2));
    *(__half*)(g_Bhi[k] + off) = __float2half_rn(w);
}

// ---------------------------------------------------------------------------
// Phase 2: persistent h-chunk HMMA GEMM, rolling plane ring.
// CTA = 256 px x 64 out x 8 h-rows, 512 threads (16 warps: 8m x 2n).
// This round: batched-MLP plane loads, cp.async gates/B, hoisted swizzles.
// ---------------------------------------------------------------------------
#define PLANE   33792                       // 258*128 padded
#define SM_FEAT 0
#define SM_BW   (4 * PLANE)                 // 135168
#define SM_SG   (SM_BW + 9 * 8192)          // 208896
#define SM_BN   (SM_SG + 2 * 9 * 256 * 4)   // 227328
#define SM_TOTAL (SM_BN + 512)              // 227840

static __device__ __forceinline__ void load_plane(
    char* sm, int slot, int hh, int w0, const float* __restrict__ xf, int tid)
{
    char* plane = sm + SM_FEAT + slot * PLANE;
    bool hv = (hh >= 0) && (hh < HH_);
    int p   = tid & 255;
    int ch0 = (tid >> 8) * 32;
    const float* rowp = xf + (size_t)hh * WW_ + w0 + p;
    uint32_t qb = (uint32_t)((p + 1) * 128);

    // two batches: 16 LDGs issued back-to-back (MLP 16), then cvt+STS
#pragma unroll
    for (int bt = 0; bt < 2; ++bt) {
        float fb[16];
#pragma unroll
        for (int j = 0; j < 8; ++j) {
            int c = ch0 + bt * 16 + 2 * j;
            fb[2 * j]     = hv ? __ldg(rowp + (size_t)c       * NPIX) : 0.0f;
            fb[2 * j + 1] = hv ? __ldg(rowp + (size_t)(c + 1) * NPIX) : 0.0f;
        }
#pragma unroll
        for (int j = 0; j < 8; ++j) {
            int c = ch0 + bt * 16 + 2 * j;
            __half2 v = __floats2half2_rn(fb[2 * j], fb[2 * j + 1]);
            *(uint32_t*)(plane + SW128(qb + (uint32_t)(c * 2))) = *(uint32_t*)&v;
        }
    }
    // halo: q=0 (w0-1), q=257 (w0+256)
    if (tid < 64) {
        int qsel = tid >> 5;
        int cc   = (tid & 31) * 2;
        int q    = qsel ? 257 : 0;
        int wg   = w0 + (qsel ? 256 : -1);
        bool v_  = hv && (wg >= 0) && (wg < WW_);
        const float* rp = xf + (size_t)hh * WW_ + wg;
        float f0 = v_ ? __ldg(rp + (size_t)cc       * NPIX) : 0.0f;
        float f1 = v_ ? __ldg(rp + (size_t)(cc + 1) * NPIX) : 0.0f;
        __half2 vv = __floats2half2_rn(f0, f1);
        *(uint32_t*)(plane + SW128((uint32_t)(q * 128 + cc * 2))) = *(uint32_t*)&vv;
    }
}

// gates via cp.async: 2304 floats = 576 x 16B chunks
static __device__ __forceinline__ void load_gates_async(
    uint32_t dst_s, int b, int h, int w0, int tid)
{
    size_t gb = (size_t)b * NPIX + (size_t)h * WW_ + w0;
    {
        int j = tid * 4;                       // chunks 0..511
        cp_async16(dst_s + (uint32_t)(tid * 16),
                   &g_s[(size_t)(j >> 8) * BN + gb + (j & 255)]);
    }
    if (tid < 64) {
        int j = (512 + tid) * 4;               // chunks 512..575
        cp_async16(dst_s + (uint32_t)((512 + tid) * 16),
                   &g_s[(size_t)(j >> 8) * BN + gb + (j & 255)]);
    }
}

__global__ __launch_bounds__(512, 1) void phase2_hmma(
    const float* __restrict__ x,
    const float* __restrict__ g2, const float* __restrict__ b2g,
    const float* __restrict__ m2, const float* __restrict__ v2,
    float* __restrict__ y)
{
    extern __shared__ char sm[];
    int tid  = threadIdx.x;
    int lane = tid & 31;
    int wid  = tid >> 5;
    int b  = blockIdx.z;
    int h0 = blockIdx.y * HCHUNK;
    int w0 = blockIdx.x * 256;

    uint32_t smb = smem_u32(sm);

    int warp_m = wid & 7;
    int warp_n = wid >> 3;
    int pbase  = warp_m * 32;
    int obase  = warp_n * 32;

    const float* xf = x + ((size_t)b * (CIN + 4) + 4) * NPIX;

    // ---- prologue: B (cp.async), BN consts, gates(h0) (cp.async), 3 planes ----
    {
        const char* srcB = (const char*)g_Bhi;
#pragma unroll
        for (int i = 0; i < 9; ++i)
            cp_async16(smb + SM_BW + (uint32_t)((tid + 512 * i) * 16),
                       srcB + (size_t)(tid + 512 * i) * 16);
    }
    load_gates_async(smb + SM_SG, b, h0, w0, tid);
    asm volatile("cp.async.commit_group;" ::: "memory");
    {
        float* sc = (float*)(sm + SM_BN);
        float* sh = sc + 64;
        if (tid < 64) {
            float a2 = g2[tid] * rsqrtf(v2[tid] + EPSV);
            sc[tid] = a2;
            sh[tid] = b2g[tid] - m2[tid] * a2;
        }
    }
    load_plane(sm, 0, h0 - 1, w0, xf, tid);
    load_plane(sm, 1, h0,     w0, xf, tid);
    load_plane(sm, 2, h0 + 1, w0, xf, tid);
    asm volatile("cp.async.wait_group 0;" ::: "memory");
    __syncthreads();

    // ---- hoisted fragment addressing: SW128(R*128+C) = R*128 + (C ^ ((R&7)<<4)) ----
    uint32_t aq   = (uint32_t)(pbase + (lane & 15));
    uint32_t acol = (uint32_t)((lane >> 4) * 16);
    uint32_t bg   = (uint32_t)(lane >> 3);
    uint32_t b_n  = (uint32_t)(obase + ((bg >> 1) << 3) + (lane & 7));
    uint32_t b_kb = (bg & 1) * 16;
    int srow = pbase + (lane >> 2);

    uint32_t arow128[3][2], axor[3][2];
#pragma unroll
    for (int q = 0; q < 3; ++q)
#pragma unroll
        for (int mt = 0; mt < 2; ++mt) {
            uint32_t r = aq + (uint32_t)q + (uint32_t)(mt * 16);
            arow128[q][mt] = r * 128;
            axor[q][mt]    = (r & 7) << 4;
        }
    uint32_t boff[2][4];
#pragma unroll
    for (int nt2 = 0; nt2 < 2; ++nt2)
#pragma unroll
        for (int ks = 0; ks < 4; ++ks) {
            uint32_t r = b_n + (uint32_t)(nt2 * 16);
            boff[nt2][ks] = r * 128 + (((uint32_t)(ks * 32) + b_kb) ^ ((r & 7) << 4));
        }

    const float* sc = (const float*)(sm + SM_BN);
    const float* sh = sc + 64;
    int rbase = pbase + (lane >> 2);
    int cbase = obase + (lane & 3) * 2;

    for (int i = 0; i < HCHUNK; ++i) {
        int h = h0 + i;

        // prefetch next gates (async, no stall), then next plane (batched LDG)
        if (i < HCHUNK - 1) {
            load_gates_async(smb + SM_SG + (uint32_t)(((i + 1) & 1) * 9216),
                             b, h + 1, w0, tid);
            asm volatile("cp.async.commit_group;" ::: "memory");
            load_plane(sm, (i + 3) & 3, h + 2, w0, xf, tid);
        }

        const float* sg = (const float*)(sm + SM_SG) + (i & 1) * 2304;

        float acc[2][4][4];
#pragma unroll
        for (int mt = 0; mt < 2; ++mt)
#pragma unroll
            for (int nt = 0; nt < 4; ++nt)
#pragma unroll
                for (int j = 0; j < 4; ++j) acc[mt][nt][j] = 0.0f;

#pragma unroll
        for (int k = 0; k < 9; ++k) {
            uint32_t pl    = smb + SM_FEAT + (uint32_t)(((i + k / 3) & 3) * PLANE);
            int      qoff  = k % 3;
            uint32_t bbase = smb + SM_BW + (uint32_t)(k * 8192);

            float tmp[2][4][4];
#pragma unroll
            for (int mt = 0; mt < 2; ++mt)
#pragma unroll
                for (int nt = 0; nt < 4; ++nt)
#pragma unroll
                    for (int j = 0; j < 4; ++j) tmp[mt][nt][j] = 0.0f;

#pragma unroll
            for (int ks = 0; ks < 4; ++ks) {
                uint32_t ah[2][4], bh[2][4];
#pragma unroll
                for (int mt = 0; mt < 2; ++mt) {
                    uint32_t off = arow128[qoff][mt] +
                                   (((uint32_t)(ks * 32) + acol) ^ axor[qoff][mt]);
                    ldsm4(pl + off, ah[mt]);
                }
#pragma unroll
                for (int nt2 = 0; nt2 < 2; ++nt2)
                    ldsm4(bbase + boff[nt2][ks], bh[nt2]);
#pragma unroll
                for (int mt = 0; mt < 2; ++mt)
#pragma unroll
                    for (int nt = 0; nt < 4; ++nt)
                        hmma(tmp[mt][nt], ah[mt], &bh[nt >> 1][(nt & 1) * 2]);
            }

#pragma unroll
            for (int mt = 0; mt < 2; ++mt) {
                float s_a = sg[k * 256 + srow + mt * 16];
                float s_b = sg[k * 256 + srow + mt * 16 + 8];
#pragma unroll
                for (int nt = 0; nt < 4; ++nt) {
                    acc[mt][nt][0] = fmaf(s_a, tmp[mt][nt][0], acc[mt][nt][0]);
                    acc[mt][nt][1] = fmaf(s_a, tmp[mt][nt][1], acc[mt][nt][1]);
                    acc[mt][nt][2] = fmaf(s_b, tmp[mt][nt][2], acc[mt][nt][2]);
                    acc[mt][nt][3] = fmaf(s_b, tmp[mt][nt][3], acc[mt][nt][3]);
                }
            }
        }

        // ---- epilogue row h ----
        float* yb = y + ((size_t)b * COUT) * NPIX + (size_t)h * WW_ + w0;
#pragma unroll
        for (int mt = 0; mt < 2; ++mt) {
#pragma unroll
            for (int nt = 0; nt < 4; ++nt) {
                int o0 = cbase + nt * 8;
                int r0 = rbase + mt * 16;
                float s0 = sc[o0], h0c = sh[o0];
                float s1 = sc[o0 + 1], h1c = sh[o0 + 1];
                yb[(size_t)o0       * NPIX + r0]     = fmaxf(fmaf(acc[mt][nt][0], s0, h0c), 0.0f);
                yb[(size_t)(o0 + 1) * NPIX + r0]     = fmaxf(fmaf(acc[mt][nt][1], s1, h1c), 0.0f);
                yb[(size_t)o0       * NPIX + r0 + 8] = fmaxf(fmaf(acc[mt][nt][2], s0, h0c), 0.0f);
                yb[(size_t)(o0 + 1) * NPIX + r0 + 8] = fmaxf(fmaf(acc[mt][nt][3], s1, h1c), 0.0f);
            }
        }

        asm volatile("cp.async.wait_group 0;" ::: "memory");
        __syncthreads();
    }
}

// ---------------------------------------------------------------------------
extern "C" void kernel_launch(void* const* d_in, const int* in_sizes, int n_in,
                              void* d_out, int out_size)
{
    const float* x     = (const float*)d_in[0];
    const int*   mask  = (const int*)  d_in[1];
    const float* W1    = (const float*)d_in[2];
    const float* bn1_g = (const float*)d_in[3];
    const float* bn1_b = (const float*)d_in[4];
    const float* bn1_m = (const float*)d_in[5];
    const float* bn1_v = (const float*)d_in[6];
    const float* W2    = (const float*)d_in[7];
    const float* b2    = (const float*)d_in[8];
    const float* Wagg  = (const float*)d_in[9];
    const float* bn2_g = (const float*)d_in[10];
    const float* bn2_b = (const float*)d_in[11];
    const float* bn2_m = (const float*)d_in[12];
    const float* bn2_v = (const float*)d_in[13];
    float* y = (float*)d_out;

    static int smem_set = 0;
    if (!smem_set) {
        cudaFuncSetAttribute(phase2_hmma, cudaFuncAttributeMaxDynamicSharedMemorySize,
                             SM_TOTAL);
        smem_set = 1;
    }

    prep_B<<<576, 64>>>(Wagg);
    phase1_gates<<<BN / 256, 256>>>(x, mask, W1, bn1_g, bn1_b, bn1_m, bn1_v, W2, b2);

    dim3 grid(WW_ / 256, HH_ / HCHUNK, BB);
    phase2_hmma<<<grid, 512, SM_TOTAL>>>(x, bn2_g, bn2_b, bn2_m, bn2_v, y);
}

// round 15
// speedup vs baseline: 1.5626x; 1.0658x over previous
#include <cuda_runtime.h>
#include <cuda_fp16.h>
#include <stdint.h>
#include <math.h>

#define EPSV 1e-5f
#define BB   2
#define CIN  64
#define COUT 64
#define HH_  64
#define WW_  2048
#define NPIX (HH_ * WW_)      // 131072
#define BN   (BB * NPIX)      // 262144
#define HCHUNK 8

// Softmax gate scratch: s[k][b*NPIX + n], 9 coalesced planes (9.4 MB)
__device__ float g_s[9 * BN];
// Pre-swizzled fp16 Wagg tiles: per k-chunk, 64 rows (o) x 128B (64 c fp16)
__device__ __align__(16) unsigned char g_Bhi[9][8192];

#define SW128(b) ((b) ^ (((b) >> 3) & 0x70))

static __device__ __forceinline__ uint32_t smem_u32(const void* p) {
    uint32_t a;
    asm("{ .reg .u64 t; cvta.to.shared.u64 t, %1; cvt.u32.u64 %0, t; }"
        : "=r"(a) : "l"(p));
    return a;
}

static __device__ __forceinline__ void cp_async16(uint32_t saddr, const void* gptr) {
    asm volatile("cp.async.ca.shared.global [%0], [%1], 16;"
                 :: "r"(saddr), "l"(gptr) : "memory");
}

static __device__ __forceinline__ void ldsm4(uint32_t addr, uint32_t* r) {
    asm volatile("ldmatrix.sync.aligned.m8n8.x4.shared.b16 {%0,%1,%2,%3}, [%4];"
                 : "=r"(r[0]), "=r"(r[1]), "=r"(r[2]), "=r"(r[3]) : "r"(addr));
}

static __device__ __forceinline__ void hmma(float* c, const uint32_t* a, const uint32_t* b) {
    asm volatile("mma.sync.aligned.m16n8k16.row.col.f32.f16.f16.f32 "
                 "{%0,%1,%2,%3}, {%4,%5,%6,%7}, {%8,%9}, {%0,%1,%2,%3};"
                 : "+f"(c[0]), "+f"(c[1]), "+f"(c[2]), "+f"(c[3])
                 : "r"(a[0]), "r"(a[1]), "r"(a[2]), "r"(a[3]), "r"(b[0]), "r"(b[1]));
}

// ---- packed f32x2 helpers (fma.rn.f32x2 is sm_100+ base ISA; no max.f32x2) ----
static __device__ __forceinline__ uint64_t pk2(float lo, float hi) {
    uint64_t r; asm("mov.b64 %0, {%1, %2};" : "=l"(r) : "f"(lo), "f"(hi)); return r;
}
static __device__ __forceinline__ uint64_t fma2(uint64_t a, uint64_t b, uint64_t c) {
    uint64_t r; asm("fma.rn.f32x2 %0, %1, %2, %3;" : "=l"(r) : "l"(a), "l"(b), "l"(c)); return r;
}
static __device__ __forceinline__ void upk2(uint64_t v, float& lo, float& hi) {
    asm("mov.b64 {%0, %1}, %2;" : "=f"(lo), "=f"(hi) : "l"(v));
}
// relu on a packed pair: unpack (register renaming, free) + 2 scalar FMAX + repack
static __device__ __forceinline__ uint64_t relu2(uint64_t v) {
    float lo, hi;
    upk2(v, lo, hi);
    return pk2(fmaxf(lo, 0.0f), fmaxf(hi, 0.0f));
}

// ---------------------------------------------------------------------------
// Phase 1: per-pixel 9-way softmax gates; packed f32x2 k-pairs + const center.
// k-pairs: {0,1},{2,3},{5,6},{7,8}; k=4 has d=0 -> logit is a CTA constant.
// ---------------------------------------------------------------------------
__global__ __launch_bounds__(256) void phase1_gates(
    const float* __restrict__ x, const int* __restrict__ mask,
    const float* __restrict__ W1, const float* __restrict__ g1,
    const float* __restrict__ b1, const float* __restrict__ m1,
    const float* __restrict__ v1, const float* __restrict__ W2,
    const float* __restrict__ b2)
{
    __shared__ float4 sW1[CIN];
    __shared__ float2 sBW[CIN];
    __shared__ float s_part[2];

    int tid = threadIdx.x;
    if (tid < CIN) {
        float a = g1[tid] * rsqrtf(v1[tid] + EPSV);
        sW1[tid] = make_float4(W1[tid * 4 + 0] * a, W1[tid * 4 + 1] * a,
                               W1[tid * 4 + 2] * a, W1[tid * 4 + 3] * a);
        sBW[tid] = make_float2(b1[tid] - m1[tid] * a, W2[tid]);
    }
    __syncthreads();

    // center-k constant: sum_c relu(b'_c) * W2_c  (threads 0..63 reduce)
    if (tid < 64) {
        float2 bw = sBW[tid];
        float val = fmaxf(bw.x, 0.0f) * bw.y;
#pragma unroll
        for (int o = 16; o > 0; o >>= 1)
            val += __shfl_down_sync(0xffffffffu, val, o);
        if ((tid & 31) == 0) s_part[tid >> 5] = val;
    }
    __syncthreads();
    float b2v = __ldg(b2);
    float c4 = s_part[0] + s_part[1] + b2v;

    int g = blockIdx.x * 256 + tid;
    int b = g / NPIX;
    int n = g - b * NPIX;
    int h = n / WW_;
    int w = n - h * WW_;

    const float* xb = x + (size_t)b * (CIN + 4) * NPIX;
    const int*   mb = mask + (size_t)b * NPIX;

    float c0 = xb[0 * NPIX + n];
    float c1 = xb[1 * NPIX + n];
    float c2 = xb[2 * NPIX + n];
    float c3 = xb[3 * NPIX + n];

    float d0[9], d1[9], d2[9], d3[9];
    bool  act[9];
#pragma unroll
    for (int k = 0; k < 9; ++k) {
        if (k == 4) { act[4] = (mb[n] != 0); continue; }
        int kh = k / 3 - 1, kw = k % 3 - 1;
        int hh = h + kh, ww = w + kw;
        bool valid = (hh >= 0) && (hh < HH_) && (ww >= 0) && (ww < WW_);
        int nn = valid ? (hh * WW_ + ww) : n;
        act[k] = valid && (mb[nn] != 0);
        d0[k] = xb[0 * NPIX + nn] - c0;
        d1[k] = xb[1 * NPIX + nn] - c1;
        d2[k] = xb[2 * NPIX + nn] - c2;
        d3[k] = xb[3 * NPIX + nn] - c3;
    }

    // pack 4 k-pairs (skip center k=4)
    const int ka[4] = {0, 2, 5, 7};
    uint64_t pd0[4], pd1[4], pd2[4], pd3[4], lgp[4];
#pragma unroll
    for (int kp = 0; kp < 4; ++kp) {
        int klo = ka[kp], khi = ka[kp] + 1;
        pd0[kp] = pk2(d0[klo], d0[khi]);
        pd1[kp] = pk2(d1[klo], d1[khi]);
        pd2[kp] = pk2(d2[klo], d2[khi]);
        pd3[kp] = pk2(d3[klo], d3[khi]);
        lgp[kp] = pk2(b2v, b2v);
    }

    for (int c = 0; c < CIN; ++c) {
        float4 wv = sW1[c];
        float2 bw = sBW[c];
        uint64_t wx2 = pk2(wv.x, wv.x);
        uint64_t wy2 = pk2(wv.y, wv.y);
        uint64_t wz2 = pk2(wv.z, wv.z);
        uint64_t ww2 = pk2(wv.w, wv.w);
        uint64_t bb2 = pk2(bw.x, bw.x);
        uint64_t w22 = pk2(bw.y, bw.y);
#pragma unroll
        for (int kp = 0; kp < 4; ++kp) {
            uint64_t t2 = fma2(pd0[kp], wx2, bb2);
            t2 = fma2(pd1[kp], wy2, t2);
            t2 = fma2(pd2[kp], wz2, t2);
            t2 = fma2(pd3[kp], ww2, t2);
            t2 = relu2(t2);
            lgp[kp] = fma2(t2, w22, lgp[kp]);
        }
    }

    float lg[9];
    lg[4] = c4;
#pragma unroll
    for (int kp = 0; kp < 4; ++kp)
        upk2(lgp[kp], lg[ka[kp]], lg[ka[kp] + 1]);

#pragma unroll
    for (int k = 0; k < 9; ++k) lg[k] = act[k] ? lg[k] : 0.0f;

    float mx = lg[0];
#pragma unroll
    for (int k = 1; k < 9; ++k) mx = fmaxf(mx, lg[k]);
    float e[9], sum = 0.0f;
#pragma unroll
    for (int k = 0; k < 9; ++k) { e[k] = __expf(lg[k] - mx); sum += e[k]; }
    float inv = __frcp_rn(sum);
#pragma unroll
    for (int k = 0; k < 9; ++k) g_s[k * BN + g] = e[k] * inv;
}

// ---------------------------------------------------------------------------
// Prep: Wagg -> fp16 SW128-swizzled smem image per k-chunk.
// ---------------------------------------------------------------------------
__global__ void prep_B(const float* __restrict__ Wagg)
{
    int kc = blockIdx.x;      // 0..575
    int o  = threadIdx.x;     // 0..63
    int k = kc >> 6, c = kc & 63;
    float w = Wagg[(size_t)o * 576 + kc];
    uint32_t off = SW128((uint32_t)(o * 128 + c * 2));
    *(__half*)(g_Bhi[k] + off) = __float2half_rn(w);
}

// ---------------------------------------------------------------------------
// Phase 2: persistent h-chunk HMMA GEMM, rolling plane ring (unchanged R13).
// ---------------------------------------------------------------------------
#define PLANE   33792                       // 258*128 padded
#define SM_FEAT 0
#define SM_BW   (4 * PLANE)                 // 135168
#define SM_SG   (SM_BW + 9 * 8192)          // 208896
#define SM_BN   (SM_SG + 2 * 9 * 256 * 4)   // 227328
#define SM_TOTAL (SM_BN + 512)              // 227840

static __device__ __forceinline__ void load_plane(
    char* sm, int slot, int hh, int w0, const float* __restrict__ xf, int tid)
{
    char* plane = sm + SM_FEAT + slot * PLANE;
    bool hv = (hh >= 0) && (hh < HH_);
    int p   = tid & 255;
    int ch0 = (tid >> 8) * 32;
    const float* rowp = xf + (size_t)hh * WW_ + w0 + p;
    uint32_t qb = (uint32_t)((p + 1) * 128);

#pragma unroll
    for (int bt = 0; bt < 2; ++bt) {
        float fb[16];
#pragma unroll
        for (int j = 0; j < 8; ++j) {
            int c = ch0 + bt * 16 + 2 * j;
            fb[2 * j]     = hv ? __ldg(rowp + (size_t)c       * NPIX) : 0.0f;
            fb[2 * j + 1] = hv ? __ldg(rowp + (size_t)(c + 1) * NPIX) : 0.0f;
        }
#pragma unroll
        for (int j = 0; j < 8; ++j) {
            int c = ch0 + bt * 16 + 2 * j;
            __half2 v = __floats2half2_rn(fb[2 * j], fb[2 * j + 1]);
            *(uint32_t*)(plane + SW128(qb + (uint32_t)(c * 2))) = *(uint32_t*)&v;
        }
    }
    if (tid < 64) {
        int qsel = tid >> 5;
        int cc   = (tid & 31) * 2;
        int q    = qsel ? 257 : 0;
        int wg   = w0 + (qsel ? 256 : -1);
        bool v_  = hv && (wg >= 0) && (wg < WW_);
        const float* rp = xf + (size_t)hh * WW_ + wg;
        float f0 = v_ ? __ldg(rp + (size_t)cc       * NPIX) : 0.0f;
        float f1 = v_ ? __ldg(rp + (size_t)(cc + 1) * NPIX) : 0.0f;
        __half2 vv = __floats2half2_rn(f0, f1);
        *(uint32_t*)(plane + SW128((uint32_t)(q * 128 + cc * 2))) = *(uint32_t*)&vv;
    }
}

static __device__ __forceinline__ void load_gates_async(
    uint32_t dst_s, int b, int h, int w0, int tid)
{
    size_t gb = (size_t)b * NPIX + (size_t)h * WW_ + w0;
    {
        int j = tid * 4;
        cp_async16(dst_s + (uint32_t)(tid * 16),
                   &g_s[(size_t)(j >> 8) * BN + gb + (j & 255)]);
    }
    if (tid < 64) {
        int j = (512 + tid) * 4;
        cp_async16(dst_s + (uint32_t)((512 + tid) * 16),
                   &g_s[(size_t)(j >> 8) * BN + gb + (j & 255)]);
    }
}

__global__ __launch_bounds__(512, 1) void phase2_hmma(
    const float* __restrict__ x,
    const float* __restrict__ g2, const float* __restrict__ b2g,
    const float* __restrict__ m2, const float* __restrict__ v2,
    float* __restrict__ y)
{
    extern __shared__ char sm[];
    int tid  = threadIdx.x;
    int lane = tid & 31;
    int wid  = tid >> 5;
    int b  = blockIdx.z;
    int h0 = blockIdx.y * HCHUNK;
    int w0 = blockIdx.x * 256;

    uint32_t smb = smem_u32(sm);

    int warp_m = wid & 7;
    int warp_n = wid >> 3;
    int pbase  = warp_m * 32;
    int obase  = warp_n * 32;

    const float* xf = x + ((size_t)b * (CIN + 4) + 4) * NPIX;

    {
        const char* srcB = (const char*)g_Bhi;
#pragma unroll
        for (int i = 0; i < 9; ++i)
            cp_async16(smb + SM_BW + (uint32_t)((tid + 512 * i) * 16),
                       srcB + (size_t)(tid + 512 * i) * 16);
    }
    load_gates_async(smb + SM_SG, b, h0, w0, tid);
    asm volatile("cp.async.commit_group;" ::: "memory");
    {
        float* sc = (float*)(sm + SM_BN);
        float* sh = sc + 64;
        if (tid < 64) {
            float a2 = g2[tid] * rsqrtf(v2[tid] + EPSV);
            sc[tid] = a2;
            sh[tid] = b2g[tid] - m2[tid] * a2;
        }
    }
    load_plane(sm, 0, h0 - 1, w0, xf, tid);
    load_plane(sm, 1, h0,     w0, xf, tid);
    load_plane(sm, 2, h0 + 1, w0, xf, tid);
    asm volatile("cp.async.wait_group 0;" ::: "memory");
    __syncthreads();

    uint32_t aq   = (uint32_t)(pbase + (lane & 15));
    uint32_t acol = (uint32_t)((lane >> 4) * 16);
    uint32_t bg   = (uint32_t)(lane >> 3);
    uint32_t b_n  = (uint32_t)(obase + ((bg >> 1) << 3) + (lane & 7));
    uint32_t b_kb = (bg & 1) * 16;
    int srow = pbase + (lane >> 2);

    uint32_t arow128[3][2], axor[3][2];
#pragma unroll
    for (int q = 0; q < 3; ++q)
#pragma unroll
        for (int mt = 0; mt < 2; ++mt) {
            uint32_t r = aq + (uint32_t)q + (uint32_t)(mt * 16);
            arow128[q][mt] = r * 128;
            axor[q][mt]    = (r & 7) << 4;
        }
    uint32_t boff[2][4];
#pragma unroll
    for (int nt2 = 0; nt2 < 2; ++nt2)
#pragma unroll
        for (int ks = 0; ks < 4; ++ks) {
            uint32_t r = b_n + (uint32_t)(nt2 * 16);
            boff[nt2][ks] = r * 128 + (((uint32_t)(ks * 32) + b_kb) ^ ((r & 7) << 4));
        }

    const float* sc = (const float*)(sm + SM_BN);
    const float* sh = sc + 64;
    int rbase = pbase + (lane >> 2);
    int cbase = obase + (lane & 3) * 2;

    for (int i = 0; i < HCHUNK; ++i) {
        int h = h0 + i;

        if (i < HCHUNK - 1) {
            load_gates_async(smb + SM_SG + (uint32_t)(((i + 1) & 1) * 9216),
                             b, h + 1, w0, tid);
            asm volatile("cp.async.commit_group;" ::: "memory");
            load_plane(sm, (i + 3) & 3, h + 2, w0, xf, tid);
        }

        const float* sg = (const float*)(sm + SM_SG) + (i & 1) * 2304;

        float acc[2][4][4];
#pragma unroll
        for (int mt = 0; mt < 2; ++mt)
#pragma unroll
            for (int nt = 0; nt < 4; ++nt)
#pragma unroll
                for (int j = 0; j < 4; ++j) acc[mt][nt][j] = 0.0f;

#pragma unroll
        for (int k = 0; k < 9; ++k) {
            uint32_t pl    = smb + SM_FEAT + (uint32_t)(((i + k / 3) & 3) * PLANE);
            int      qoff  = k % 3;
            uint32_t bbase = smb + SM_BW + (uint32_t)(k * 8192);

            float tmp[2][4][4];
#pragma unroll
            for (int mt = 0; mt < 2; ++mt)
#pragma unroll
                for (int nt = 0; nt < 4; ++nt)
#pragma unroll
                    for (int j = 0; j < 4; ++j) tmp[mt][nt][j] = 0.0f;

#pragma unroll
            for (int ks = 0; ks < 4; ++ks) {
                uint32_t ah[2][4], bh[2][4];
#pragma unroll
                for (int mt = 0; mt < 2; ++mt) {
                    uint32_t off = arow128[qoff][mt] +
                                   (((uint32_t)(ks * 32) + acol) ^ axor[qoff][mt]);
                    ldsm4(pl + off, ah[mt]);
                }
#pragma unroll
                for (int nt2 = 0; nt2 < 2; ++nt2)
                    ldsm4(bbase + boff[nt2][ks], bh[nt2]);
#pragma unroll
                for (int mt = 0; mt < 2; ++mt)
#pragma unroll
                    for (int nt = 0; nt < 4; ++nt)
                        hmma(tmp[mt][nt], ah[mt], &bh[nt >> 1][(nt & 1) * 2]);
            }

#pragma unroll
            for (int mt = 0; mt < 2; ++mt) {
                float s_a = sg[k * 256 + srow + mt * 16];
                float s_b = sg[k * 256 + srow + mt * 16 + 8];
#pragma unroll
                for (int nt = 0; nt < 4; ++nt) {
                    acc[mt][nt][0] = fmaf(s_a, tmp[mt][nt][0], acc[mt][nt][0]);
                    acc[mt][nt][1] = fmaf(s_a, tmp[mt][nt][1], acc[mt][nt][1]);
                    acc[mt][nt][2] = fmaf(s_b, tmp[mt][nt][2], acc[mt][nt][2]);
                    acc[mt][nt][3] = fmaf(s_b, tmp[mt][nt][3], acc[mt][nt][3]);
                }
            }
        }

        float* yb = y + ((size_t)b * COUT) * NPIX + (size_t)h * WW_ + w0;
#pragma unroll
        for (int mt = 0; mt < 2; ++mt) {
#pragma unroll
            for (int nt = 0; nt < 4; ++nt) {
                int o0 = cbase + nt * 8;
                int r0 = rbase + mt * 16;
                float s0 = sc[o0], h0c = sh[o0];
                float s1 = sc[o0 + 1], h1c = sh[o0 + 1];
                yb[(size_t)o0       * NPIX + r0]     = fmaxf(fmaf(acc[mt][nt][0], s0, h0c), 0.0f);
                yb[(size_t)(o0 + 1) * NPIX + r0]     = fmaxf(fmaf(acc[mt][nt][1], s1, h1c), 0.0f);
                yb[(size_t)o0       * NPIX + r0 + 8] = fmaxf(fmaf(acc[mt][nt][2], s0, h0c), 0.0f);
                yb[(size_t)(o0 + 1) * NPIX + r0 + 8] = fmaxf(fmaf(acc[mt][nt][3], s1, h1c), 0.0f);
            }
        }

        asm volatile("cp.async.wait_group 0;" ::: "memory");
        __syncthreads();
    }
}

// ---------------------------------------------------------------------------
extern "C" void kernel_launch(void* const* d_in, const int* in_sizes, int n_in,
                              void* d_out, int out_size)
{
    const float* x     = (const float*)d_in[0];
    const int*   mask  = (const int*)  d_in[1];
    const float* W1    = (const float*)d_in[2];
    const float* bn1_g = (const float*)d_in[3];
    const float* bn1_b = (const float*)d_in[4];
    const float* bn1_m = (const float*)d_in[5];
    const float* bn1_v = (const float*)d_in[6];
    const float* W2    = (const float*)d_in[7];
    const float* b2    = (const float*)d_in[8];
    const float* Wagg  = (const float*)d_in[9];
    const float* bn2_g = (const float*)d_in[10];
    const float* bn2_b = (const float*)d_in[11];
    const float* bn2_m = (const float*)d_in[12];
    const float* bn2_v = (const float*)d_in[13];
    float* y = (float*)d_out;

    static int smem_set = 0;
    if (!smem_set) {
        cudaFuncSetAttribute(phase2_hmma, cudaFuncAttributeMaxDynamicSharedMemorySize,
                             SM_TOTAL);
        smem_set = 1;
    }

    prep_B<<<576, 64>>>(Wagg);
    phase1_gates<<<BN / 256, 256>>>(x, mask, W1, bn1_g, bn1_b, bn1_m, bn1_v, W2, b2);

    dim3 grid(WW_ / 256, HH_ / HCHUNK, BB);
    phase2_hmma<<<grid, 512, SM_TOTAL>>>(x, bn2_g, bn2_b, bn2_m, bn2_v, y);
}

// round 16
// speedup vs baseline: 1.5831x; 1.0131x over previous
#include <cuda_runtime.h>
#include <cuda_fp16.h>
#include <stdint.h>
#include <math.h>

#define EPSV 1e-5f
#define BB   2
#define CIN  64
#define COUT 64
#define HH_  64
#define WW_  2048
#define NPIX (HH_ * WW_)      // 131072
#define HCHUNK 8

#define SW128(b) ((b) ^ (((b) >> 3) & 0x70))

static __device__ __forceinline__ uint32_t smem_u32(const void* p) {
    uint32_t a;
    asm("{ .reg .u64 t; cvta.to.shared.u64 t, %1; cvt.u32.u64 %0, t; }"
        : "=r"(a) : "l"(p));
    return a;
}

static __device__ __forceinline__ void ldsm4(uint32_t addr, uint32_t* r) {
    asm volatile("ldmatrix.sync.aligned.m8n8.x4.shared.b16 {%0,%1,%2,%3}, [%4];"
                 : "=r"(r[0]), "=r"(r[1]), "=r"(r[2]), "=r"(r[3]) : "r"(addr));
}

static __device__ __forceinline__ void hmma(float* c, const uint32_t* a, const uint32_t* b) {
    asm volatile("mma.sync.aligned.m16n8k16.row.col.f32.f16.f16.f32 "
                 "{%0,%1,%2,%3}, {%4,%5,%6,%7}, {%8,%9}, {%0,%1,%2,%3};"
                 : "+f"(c[0]), "+f"(c[1]), "+f"(c[2]), "+f"(c[3])
                 : "r"(a[0]), "r"(a[1]), "r"(a[2]), "r"(a[3]), "r"(b[0]), "r"(b[1]));
}

// ---- packed f32x2 helpers (fma.rn.f32x2 only; no max.f32x2 in PTX) ----
static __device__ __forceinline__ uint64_t pk2(float lo, float hi) {
    uint64_t r; asm("mov.b64 %0, {%1, %2};" : "=l"(r) : "f"(lo), "f"(hi)); return r;
}
static __device__ __forceinline__ uint64_t fma2(uint64_t a, uint64_t b, uint64_t c) {
    uint64_t r; asm("fma.rn.f32x2 %0, %1, %2, %3;" : "=l"(r) : "l"(a), "l"(b), "l"(c)); return r;
}
static __device__ __forceinline__ void upk2(uint64_t v, float& lo, float& hi) {
    asm("mov.b64 {%0, %1}, %2;" : "=f"(lo), "=f"(hi) : "l"(v));
}
static __device__ __forceinline__ uint64_t relu2(uint64_t v) {
    float lo, hi;
    upk2(v, lo, hi);
    return pk2(fmaxf(lo, 0.0f), fmaxf(hi, 0.0f));
}

// ---------------------------------------------------------------------------
// smem layout (230928 B < 232448 cap, 1 CTA/SM)
// ---------------------------------------------------------------------------
#define PLANE   33792                       // 258*128 padded
#define SM_FEAT 0                           // 4 plane ring
#define SM_BW   (4 * PLANE)                 // 135168: B fp16 swizzled [9][8192]
#define SM_SG   (SM_BW + 9 * 8192)          // 208896: gates [2][9*256] fp32
#define SM_WP   (SM_SG + 2 * 2304 * 4)      // 227328: packed gate weights 64*6*u64
#define SM_BN   (SM_WP + 3072)              // 230400: BN2 scale[64], shift[64]
#define SM_C4   (SM_BN + 512)               // 230912: c4 partials [2]
#define SM_TOTAL 230928

// ---------------------------------------------------------------------------
// per-pixel gate computation (exact R15 phase1 math), writes sg[k*256+p]
// ---------------------------------------------------------------------------
static __device__ __forceinline__ void compute_gates(
    char* sm, float* sgbuf, int b, int hg, int w0, int p,
    const float* __restrict__ x, const int* __restrict__ mask, float b2v)
{
    int wpix = w0 + p;
    int n = hg * WW_ + wpix;
    const float* xb = x + (size_t)b * (CIN + 4) * NPIX;
    const int*   mb = mask + (size_t)b * NPIX;

    const float* c4p = (const float*)(sm + SM_C4);
    float c4 = c4p[0] + c4p[1] + b2v;

    float c0 = xb[0 * NPIX + n];
    float c1 = xb[1 * NPIX + n];
    float c2 = xb[2 * NPIX + n];
    float c3 = xb[3 * NPIX + n];

    float d0[9], d1[9], d2[9], d3[9];
    bool  act[9];
#pragma unroll
    for (int k = 0; k < 9; ++k) {
        if (k == 4) { act[4] = (mb[n] != 0); continue; }
        int kh = k / 3 - 1, kw = k % 3 - 1;
        int hh = hg + kh, ww = wpix + kw;
        bool valid = (hh >= 0) && (hh < HH_) && (ww >= 0) && (ww < WW_);
        int nn = valid ? (hh * WW_ + ww) : n;
        act[k] = valid && (mb[nn] != 0);
        d0[k] = xb[0 * NPIX + nn] - c0;
        d1[k] = xb[1 * NPIX + nn] - c1;
        d2[k] = xb[2 * NPIX + nn] - c2;
        d3[k] = xb[3 * NPIX + nn] - c3;
    }

    const int ka[4] = {0, 2, 5, 7};
    uint64_t pd0[4], pd1[4], pd2[4], pd3[4], lgp[4];
#pragma unroll
    for (int kp = 0; kp < 4; ++kp) {
        int klo = ka[kp], khi = ka[kp] + 1;
        pd0[kp] = pk2(d0[klo], d0[khi]);
        pd1[kp] = pk2(d1[klo], d1[khi]);
        pd2[kp] = pk2(d2[klo], d2[khi]);
        pd3[kp] = pk2(d3[klo], d3[khi]);
        lgp[kp] = pk2(b2v, b2v);
    }

    const ulonglong2* wpv = (const ulonglong2*)(sm + SM_WP);
    for (int c = 0; c < CIN; ++c) {
        ulonglong2 qa = wpv[c * 3 + 0];
        ulonglong2 qb = wpv[c * 3 + 1];
        ulonglong2 qc = wpv[c * 3 + 2];
#pragma unroll
        for (int kp = 0; kp < 4; ++kp) {
            uint64_t t2 = fma2(pd0[kp], qa.x, qc.x);
            t2 = fma2(pd1[kp], qa.y, t2);
            t2 = fma2(pd2[kp], qb.x, t2);
            t2 = fma2(pd3[kp], qb.y, t2);
            t2 = relu2(t2);
            lgp[kp] = fma2(t2, qc.y, lgp[kp]);
        }
    }

    float lg[9];
    lg[4] = c4;
#pragma unroll
    for (int kp = 0; kp < 4; ++kp)
        upk2(lgp[kp], lg[ka[kp]], lg[ka[kp] + 1]);

#pragma unroll
    for (int k = 0; k < 9; ++k) lg[k] = act[k] ? lg[k] : 0.0f;

    float mx = lg[0];
#pragma unroll
    for (int k = 1; k < 9; ++k) mx = fmaxf(mx, lg[k]);
    float e[9], sum = 0.0f;
#pragma unroll
    for (int k = 0; k < 9; ++k) { e[k] = __expf(lg[k] - mx); sum += e[k]; }
    float inv = __frcp_rn(sum);
#pragma unroll
    for (int k = 0; k < 9; ++k) sgbuf[k * 256 + p] = e[k] * inv;
}

// ---------------------------------------------------------------------------
// feature plane loader for threads 256-511 (t = tid - 256, 0..255)
// ---------------------------------------------------------------------------
static __device__ __forceinline__ void load_plane256(
    char* sm, int slot, int hh, int w0, const float* __restrict__ xf, int t)
{
    char* plane = sm + SM_FEAT + slot * PLANE;
    bool hv = (hh >= 0) && (hh < HH_);
    const float* rowp = xf + (size_t)hh * WW_ + w0 + t;
    uint32_t qb = (uint32_t)((t + 1) * 128);

#pragma unroll
    for (int bt = 0; bt < 4; ++bt) {
        float fb[16];
#pragma unroll
        for (int j = 0; j < 8; ++j) {
            int c = bt * 16 + 2 * j;
            fb[2 * j]     = hv ? __ldg(rowp + (size_t)c       * NPIX) : 0.0f;
            fb[2 * j + 1] = hv ? __ldg(rowp + (size_t)(c + 1) * NPIX) : 0.0f;
        }
#pragma unroll
        for (int j = 0; j < 8; ++j) {
            int c = bt * 16 + 2 * j;
            __half2 v = __floats2half2_rn(fb[2 * j], fb[2 * j + 1]);
            *(uint32_t*)(plane + SW128(qb + (uint32_t)(c * 2))) = *(uint32_t*)&v;
        }
    }
    if (t < 64) {
        int qsel = t >> 5;
        int cc   = (t & 31) * 2;
        int q    = qsel ? 257 : 0;
        int wg   = w0 + (qsel ? 256 : -1);
        bool v_  = hv && (wg >= 0) && (wg < WW_);
        const float* rp = xf + (size_t)hh * WW_ + wg;
        float f0 = v_ ? __ldg(rp + (size_t)cc       * NPIX) : 0.0f;
        float f1 = v_ ? __ldg(rp + (size_t)(cc + 1) * NPIX) : 0.0f;
        __half2 vv = __floats2half2_rn(f0, f1);
        *(uint32_t*)(plane + SW128((uint32_t)(q * 128 + cc * 2))) = *(uint32_t*)&vv;
    }
}

// ---------------------------------------------------------------------------
// Fused kernel: gates + HMMA GEMM + BN2/ReLU. 512 threads, 128 CTAs (1 wave).
// ---------------------------------------------------------------------------
__global__ __launch_bounds__(512, 1) void fused_pac(
    const float* __restrict__ x, const int* __restrict__ mask,
    const float* __restrict__ W1, const float* __restrict__ g1,
    const float* __restrict__ b1, const float* __restrict__ m1,
    const float* __restrict__ v1, const float* __restrict__ W2,
    const float* __restrict__ b2, const float* __restrict__ Wagg,
    const float* __restrict__ g2, const float* __restrict__ b2g,
    const float* __restrict__ m2, const float* __restrict__ v2,
    float* __restrict__ y)
{
    extern __shared__ char sm[];
    int tid  = threadIdx.x;
    int lane = tid & 31;
    int wid  = tid >> 5;
    int b  = blockIdx.z;
    int h0 = blockIdx.y * HCHUNK;
    int w0 = blockIdx.x * 256;

    uint32_t smb = smem_u32(sm);
    float b2v = __ldg(b2);

    int warp_m = wid & 7;
    int warp_n = wid >> 3;
    int pbase  = warp_m * 32;
    int obase  = warp_n * 32;

    const float* xf = x + ((size_t)b * (CIN + 4) + 4) * NPIX;

    // ---- prologue 1: convert Wagg -> fp16 swizzled B tiles (all threads) ----
#pragma unroll 8
    for (int it = 0; it < 72; ++it) {
        int e = tid + 512 * it;          // 0..36863
        int o = e / 576;
        int r = e - o * 576;
        int k = r >> 6, c = r & 63;
        float w = Wagg[e];
        *(__half*)(sm + SM_BW + k * 8192 + SW128((uint32_t)(o * 128 + c * 2))) =
            __float2half_rn(w);
    }

    // ---- prologue 2: fold gate weights, BN2 consts, c4 partials ----
    if (tid < 64) {
        float a = g1[tid] * rsqrtf(v1[tid] + EPSV);
        float wx = W1[tid * 4 + 0] * a, wy = W1[tid * 4 + 1] * a;
        float wz = W1[tid * 4 + 2] * a, ww = W1[tid * 4 + 3] * a;
        float bb = b1[tid] - m1[tid] * a;
        float w2 = W2[tid];
        uint64_t* wp = (uint64_t*)(sm + SM_WP);
        wp[tid * 6 + 0] = pk2(wx, wx);
        wp[tid * 6 + 1] = pk2(wy, wy);
        wp[tid * 6 + 2] = pk2(wz, wz);
        wp[tid * 6 + 3] = pk2(ww, ww);
        wp[tid * 6 + 4] = pk2(bb, bb);
        wp[tid * 6 + 5] = pk2(w2, w2);

        float a2 = g2[tid] * rsqrtf(v2[tid] + EPSV);
        ((float*)(sm + SM_BN))[tid]      = a2;
        ((float*)(sm + SM_BN))[64 + tid] = b2g[tid] - m2[tid] * a2;

        float val = fmaxf(bb, 0.0f) * w2;
#pragma unroll
        for (int o = 16; o > 0; o >>= 1)
            val += __shfl_down_sync(0xffffffffu, val, o);
        if ((tid & 31) == 0) ((float*)(sm + SM_C4))[tid >> 5] = val;
    }
    __syncthreads();

    // ---- prologue 3: gates(h0) by threads 0-255; 3 planes by threads 256-511 ----
    if (tid < 256) {
        compute_gates(sm, (float*)(sm + SM_SG), b, h0, w0, tid, x, mask, b2v);
    } else {
        int t = tid - 256;
        load_plane256(sm, 0, h0 - 1, w0, xf, t);
        load_plane256(sm, 1, h0,     w0, xf, t);
        load_plane256(sm, 2, h0 + 1, w0, xf, t);
    }
    __syncthreads();

    // ---- fragment addressing (hoisted swizzles) ----
    uint32_t aq   = (uint32_t)(pbase + (lane & 15));
    uint32_t acol = (uint32_t)((lane >> 4) * 16);
    uint32_t bg   = (uint32_t)(lane >> 3);
    uint32_t b_n  = (uint32_t)(obase + ((bg >> 1) << 3) + (lane & 7));
    uint32_t b_kb = (bg & 1) * 16;
    int srow = pbase + (lane >> 2);

    uint32_t arow128[3][2], axor[3][2];
#pragma unroll
    for (int q = 0; q < 3; ++q)
#pragma unroll
        for (int mt = 0; mt < 2; ++mt) {
            uint32_t r = aq + (uint32_t)q + (uint32_t)(mt * 16);
            arow128[q][mt] = r * 128;
            axor[q][mt]    = (r & 7) << 4;
        }
    uint32_t boff[2][4];
#pragma unroll
    for (int nt2 = 0; nt2 < 2; ++nt2)
#pragma unroll
        for (int ks = 0; ks < 4; ++ks) {
            uint32_t r = b_n + (uint32_t)(nt2 * 16);
            boff[nt2][ks] = r * 128 + (((uint32_t)(ks * 32) + b_kb) ^ ((r & 7) << 4));
        }

    const float* sc = (const float*)(sm + SM_BN);
    const float* sh = sc + 64;
    int rbase = pbase + (lane >> 2);
    int cbase = obase + (lane & 3) * 2;

    for (int i = 0; i < HCHUNK; ++i) {
        int h = h0 + i;

        // ---- overlap work: next-row gates (threads 0-255), next plane (256-511) ----
        if (i < HCHUNK - 1) {
            if (tid < 256) {
                compute_gates(sm, (float*)(sm + SM_SG) + ((i + 1) & 1) * 2304,
                              b, h + 1, w0, tid, x, mask, b2v);
            } else {
                load_plane256(sm, (i + 3) & 3, h + 2, w0, xf, tid - 256);
            }
        }

        const float* sg = (const float*)(sm + SM_SG) + (i & 1) * 2304;

        float acc[2][4][4];
#pragma unroll
        for (int mt = 0; mt < 2; ++mt)
#pragma unroll
            for (int nt = 0; nt < 4; ++nt)
#pragma unroll
                for (int j = 0; j < 4; ++j) acc[mt][nt][j] = 0.0f;

#pragma unroll
        for (int k = 0; k < 9; ++k) {
            uint32_t pl    = smb + SM_FEAT + (uint32_t)(((i + k / 3) & 3) * PLANE);
            int      qoff  = k % 3;
            uint32_t bbase = smb + SM_BW + (uint32_t)(k * 8192);

            float tmp[2][4][4];
#pragma unroll
            for (int mt = 0; mt < 2; ++mt)
#pragma unroll
                for (int nt = 0; nt < 4; ++nt)
#pragma unroll
                    for (int j = 0; j < 4; ++j) tmp[mt][nt][j] = 0.0f;

#pragma unroll
            for (int ks = 0; ks < 4; ++ks) {
                uint32_t ah[2][4], bh[2][4];
#pragma unroll
                for (int mt = 0; mt < 2; ++mt) {
                    uint32_t off = arow128[qoff][mt] +
                                   (((uint32_t)(ks * 32) + acol) ^ axor[qoff][mt]);
                    ldsm4(pl + off, ah[mt]);
                }
#pragma unroll
                for (int nt2 = 0; nt2 < 2; ++nt2)
                    ldsm4(bbase + boff[nt2][ks], bh[nt2]);
#pragma unroll
                for (int mt = 0; mt < 2; ++mt)
#pragma unroll
                    for (int nt = 0; nt < 4; ++nt)
                        hmma(tmp[mt][nt], ah[mt], &bh[nt >> 1][(nt & 1) * 2]);
            }

#pragma unroll
            for (int mt = 0; mt < 2; ++mt) {
                float s_a = sg[k * 256 + srow + mt * 16];
                float s_b = sg[k * 256 + srow + mt * 16 + 8];
#pragma unroll
                for (int nt = 0; nt < 4; ++nt) {
                    acc[mt][nt][0] = fmaf(s_a, tmp[mt][nt][0], acc[mt][nt][0]);
                    acc[mt][nt][1] = fmaf(s_a, tmp[mt][nt][1], acc[mt][nt][1]);
                    acc[mt][nt][2] = fmaf(s_b, tmp[mt][nt][2], acc[mt][nt][2]);
                    acc[mt][nt][3] = fmaf(s_b, tmp[mt][nt][3], acc[mt][nt][3]);
                }
            }
        }

        // ---- epilogue row h ----
        float* yb = y + ((size_t)b * COUT) * NPIX + (size_t)h * WW_ + w0;
#pragma unroll
        for (int mt = 0; mt < 2; ++mt) {
#pragma unroll
            for (int nt = 0; nt < 4; ++nt) {
                int o0 = cbase + nt * 8;
                int r0 = rbase + mt * 16;
                float s0 = sc[o0], h0c = sh[o0];
                float s1 = sc[o0 + 1], h1c = sh[o0 + 1];
                yb[(size_t)o0       * NPIX + r0]     = fmaxf(fmaf(acc[mt][nt][0], s0, h0c), 0.0f);
                yb[(size_t)(o0 + 1) * NPIX + r0]     = fmaxf(fmaf(acc[mt][nt][1], s1, h1c), 0.0f);
                yb[(size_t)o0       * NPIX + r0 + 8] = fmaxf(fmaf(acc[mt][nt][2], s0, h0c), 0.0f);
                yb[(size_t)(o0 + 1) * NPIX + r0 + 8] = fmaxf(fmaf(acc[mt][nt][3], s1, h1c), 0.0f);
            }
        }

        __syncthreads();
    }
}

// ---------------------------------------------------------------------------
extern "C" void kernel_launch(void* const* d_in, const int* in_sizes, int n_in,
                              void* d_out, int out_size)
{
    const float* x     = (const float*)d_in[0];
    const int*   mask  = (const int*)  d_in[1];
    const float* W1    = (const float*)d_in[2];
    const float* bn1_g = (const float*)d_in[3];
    const float* bn1_b = (const float*)d_in[4];
    const float* bn1_m = (const float*)d_in[5];
    const float* bn1_v = (const float*)d_in[6];
    const float* W2    = (const float*)d_in[7];
    const float* b2    = (const float*)d_in[8];
    const float* Wagg  = (const float*)d_in[9];
    const float* bn2_g = (const float*)d_in[10];
    const float* bn2_b = (const float*)d_in[11];
    const float* bn2_m = (const float*)d_in[12];
    const float* bn2_v = (const float*)d_in[13];
    float* y = (float*)d_out;

    static int smem_set = 0;
    if (!smem_set) {
        cudaFuncSetAttribute(fused_pac, cudaFuncAttributeMaxDynamicSharedMemorySize,
                             SM_TOTAL);
        smem_set = 1;
    }

    dim3 grid(WW_ / 256, HH_ / HCHUNK, BB);
    fused_pac<<<grid, 512, SM_TOTAL>>>(x, mask, W1, bn1_g, bn1_b, bn1_m, bn1_v,
                                       W2, b2, Wagg, bn2_g, bn2_b, bn2_m, bn2_v, y);
}

// round 17
// speedup vs baseline: 1.5917x; 1.0054x over previous
#include <cuda_runtime.h>
#include <cuda_fp16.h>
#include <stdint.h>
#include <math.h>

#define EPSV 1e-5f
#define BB   2
#define CIN  64
#define COUT 64
#define HH_  64
#define WW_  2048
#define NPIX (HH_ * WW_)      // 131072
#define HCHUNK 8

#define SW128(b) ((b) ^ (((b) >> 3) & 0x70))

static __device__ __forceinline__ uint32_t smem_u32(const void* p) {
    uint32_t a;
    asm("{ .reg .u64 t; cvta.to.shared.u64 t, %1; cvt.u32.u64 %0, t; }"
        : "=r"(a) : "l"(p));
    return a;
}

static __device__ __forceinline__ void ldsm4(uint32_t addr, uint32_t* r) {
    asm volatile("ldmatrix.sync.aligned.m8n8.x4.shared.b16 {%0,%1,%2,%3}, [%4];"
                 : "=r"(r[0]), "=r"(r[1]), "=r"(r[2]), "=r"(r[3]) : "r"(addr));
}

// D += A*B (accumulate in place)
static __device__ __forceinline__ void hmma(float* c, const uint32_t* a, const uint32_t* b) {
    asm volatile("mma.sync.aligned.m16n8k16.row.col.f32.f16.f16.f32 "
                 "{%0,%1,%2,%3}, {%4,%5,%6,%7}, {%8,%9}, {%0,%1,%2,%3};"
                 : "+f"(c[0]), "+f"(c[1]), "+f"(c[2]), "+f"(c[3])
                 : "r"(a[0]), "r"(a[1]), "r"(a[2]), "r"(a[3]), "r"(b[0]), "r"(b[1]));
}

// D = A*B + C (separate C input -> no tmp zero-init needed)
static __device__ __forceinline__ void hmma_c(float* d, const uint32_t* a,
                                              const uint32_t* b, const float* c) {
    asm volatile("mma.sync.aligned.m16n8k16.row.col.f32.f16.f16.f32 "
                 "{%0,%1,%2,%3}, {%4,%5,%6,%7}, {%8,%9}, {%10,%11,%12,%13};"
                 : "=f"(d[0]), "=f"(d[1]), "=f"(d[2]), "=f"(d[3])
                 : "r"(a[0]), "r"(a[1]), "r"(a[2]), "r"(a[3]), "r"(b[0]), "r"(b[1]),
                   "f"(c[0]), "f"(c[1]), "f"(c[2]), "f"(c[3]));
}

// ---- packed f32x2 helpers (fma.rn.f32x2 only; no max.f32x2 in PTX) ----
static __device__ __forceinline__ uint64_t pk2(float lo, float hi) {
    uint64_t r; asm("mov.b64 %0, {%1, %2};" : "=l"(r) : "f"(lo), "f"(hi)); return r;
}
static __device__ __forceinline__ uint64_t fma2(uint64_t a, uint64_t b, uint64_t c) {
    uint64_t r; asm("fma.rn.f32x2 %0, %1, %2, %3;" : "=l"(r) : "l"(a), "l"(b), "l"(c)); return r;
}
static __device__ __forceinline__ void upk2(uint64_t v, float& lo, float& hi) {
    asm("mov.b64 {%0, %1}, %2;" : "=f"(lo), "=f"(hi) : "l"(v));
}
static __device__ __forceinline__ uint64_t relu2(uint64_t v) {
    float lo, hi;
    upk2(v, lo, hi);
    return pk2(fmaxf(lo, 0.0f), fmaxf(hi, 0.0f));
}

// ---------------------------------------------------------------------------
// smem layout (230928 B < 232448 cap, 1 CTA/SM)
// ---------------------------------------------------------------------------
#define PLANE   33792                       // 258*128 padded
#define SM_FEAT 0                           // 4 plane ring
#define SM_BW   (4 * PLANE)                 // 135168: B fp16 swizzled [9][8192]
#define SM_SG   (SM_BW + 9 * 8192)          // 208896: gates [2][9*256] fp32
#define SM_WP   (SM_SG + 2 * 2304 * 4)      // 227328: packed gate weights 64*6*u64
#define SM_BN   (SM_WP + 3072)              // 230400: BN2 scale[64], shift[64]
#define SM_C4   (SM_BN + 512)               // 230912: c4 partials [2]
#define SM_TOTAL 230928

// ---------------------------------------------------------------------------
// per-pixel gate computation (exact R15 phase1 math), writes sg[k*256+p]
// ---------------------------------------------------------------------------
static __device__ __forceinline__ void compute_gates(
    char* sm, float* sgbuf, int b, int hg, int w0, int p,
    const float* __restrict__ x, const int* __restrict__ mask, float b2v)
{
    int wpix = w0 + p;
    int n = hg * WW_ + wpix;
    const float* xb = x + (size_t)b * (CIN + 4) * NPIX;
    const int*   mb = mask + (size_t)b * NPIX;

    const float* c4p = (const float*)(sm + SM_C4);
    float c4 = c4p[0] + c4p[1] + b2v;

    float c0 = xb[0 * NPIX + n];
    float c1 = xb[1 * NPIX + n];
    float c2 = xb[2 * NPIX + n];
    float c3 = xb[3 * NPIX + n];

    float d0[9], d1[9], d2[9], d3[9];
    bool  act[9];
#pragma unroll
    for (int k = 0; k < 9; ++k) {
        if (k == 4) { act[4] = (mb[n] != 0); continue; }
        int kh = k / 3 - 1, kw = k % 3 - 1;
        int hh = hg + kh, ww = wpix + kw;
        bool valid = (hh >= 0) && (hh < HH_) && (ww >= 0) && (ww < WW_);
        int nn = valid ? (hh * WW_ + ww) : n;
        act[k] = valid && (mb[nn] != 0);
        d0[k] = xb[0 * NPIX + nn] - c0;
        d1[k] = xb[1 * NPIX + nn] - c1;
        d2[k] = xb[2 * NPIX + nn] - c2;
        d3[k] = xb[3 * NPIX + nn] - c3;
    }

    const int ka[4] = {0, 2, 5, 7};
    uint64_t pd0[4], pd1[4], pd2[4], pd3[4], lgp[4];
#pragma unroll
    for (int kp = 0; kp < 4; ++kp) {
        int klo = ka[kp], khi = ka[kp] + 1;
        pd0[kp] = pk2(d0[klo], d0[khi]);
        pd1[kp] = pk2(d1[klo], d1[khi]);
        pd2[kp] = pk2(d2[klo], d2[khi]);
        pd3[kp] = pk2(d3[klo], d3[khi]);
        lgp[kp] = pk2(b2v, b2v);
    }

    const ulonglong2* wpv = (const ulonglong2*)(sm + SM_WP);
    for (int c = 0; c < CIN; ++c) {
        ulonglong2 qa = wpv[c * 3 + 0];
        ulonglong2 qb = wpv[c * 3 + 1];
        ulonglong2 qc = wpv[c * 3 + 2];
#pragma unroll
        for (int kp = 0; kp < 4; ++kp) {
            uint64_t t2 = fma2(pd0[kp], qa.x, qc.x);
            t2 = fma2(pd1[kp], qa.y, t2);
            t2 = fma2(pd2[kp], qb.x, t2);
            t2 = fma2(pd3[kp], qb.y, t2);
            t2 = relu2(t2);
            lgp[kp] = fma2(t2, qc.y, lgp[kp]);
        }
    }

    float lg[9];
    lg[4] = c4;
#pragma unroll
    for (int kp = 0; kp < 4; ++kp)
        upk2(lgp[kp], lg[ka[kp]], lg[ka[kp] + 1]);

#pragma unroll
    for (int k = 0; k < 9; ++k) lg[k] = act[k] ? lg[k] : 0.0f;

    float mx = lg[0];
#pragma unroll
    for (int k = 1; k < 9; ++k) mx = fmaxf(mx, lg[k]);
    float e[9], sum = 0.0f;
#pragma unroll
    for (int k = 0; k < 9; ++k) { e[k] = __expf(lg[k] - mx); sum += e[k]; }
    float inv = __frcp_rn(sum);
#pragma unroll
    for (int k = 0; k < 9; ++k) sgbuf[k * 256 + p] = e[k] * inv;
}

// ---------------------------------------------------------------------------
// feature plane loader for threads 256-511 (t = tid - 256, 0..255)
// ---------------------------------------------------------------------------
static __device__ __forceinline__ void load_plane256(
    char* sm, int slot, int hh, int w0, const float* __restrict__ xf, int t)
{
    char* plane = sm + SM_FEAT + slot * PLANE;
    bool hv = (hh >= 0) && (hh < HH_);
    const float* rowp = xf + (size_t)hh * WW_ + w0 + t;
    uint32_t qb = (uint32_t)((t + 1) * 128);

#pragma unroll
    for (int bt = 0; bt < 4; ++bt) {
        float fb[16];
#pragma unroll
        for (int j = 0; j < 8; ++j) {
            int c = bt * 16 + 2 * j;
            fb[2 * j]     = hv ? __ldg(rowp + (size_t)c       * NPIX) : 0.0f;
            fb[2 * j + 1] = hv ? __ldg(rowp + (size_t)(c + 1) * NPIX) : 0.0f;
        }
#pragma unroll
        for (int j = 0; j < 8; ++j) {
            int c = bt * 16 + 2 * j;
            __half2 v = __floats2half2_rn(fb[2 * j], fb[2 * j + 1]);
            *(uint32_t*)(plane + SW128(qb + (uint32_t)(c * 2))) = *(uint32_t*)&v;
        }
    }
    if (t < 64) {
        int qsel = t >> 5;
        int cc   = (t & 31) * 2;
        int q    = qsel ? 257 : 0;
        int wg   = w0 + (qsel ? 256 : -1);
        bool v_  = hv && (wg >= 0) && (wg < WW_);
        const float* rp = xf + (size_t)hh * WW_ + wg;
        float f0 = v_ ? __ldg(rp + (size_t)cc       * NPIX) : 0.0f;
        float f1 = v_ ? __ldg(rp + (size_t)(cc + 1) * NPIX) : 0.0f;
        __half2 vv = __floats2half2_rn(f0, f1);
        *(uint32_t*)(plane + SW128((uint32_t)(q * 128 + cc * 2))) = *(uint32_t*)&vv;
    }
}

// ---------------------------------------------------------------------------
// Fused kernel: gates + HMMA GEMM + BN2/ReLU. 512 threads, 128 CTAs (1 wave).
// R17: zero-quad C (no tmp zero-init) + packed f32x2 fold accumulators.
// ---------------------------------------------------------------------------
__global__ __launch_bounds__(512, 1) void fused_pac(
    const float* __restrict__ x, const int* __restrict__ mask,
    const float* __restrict__ W1, const float* __restrict__ g1,
    const float* __restrict__ b1, const float* __restrict__ m1,
    const float* __restrict__ v1, const float* __restrict__ W2,
    const float* __restrict__ b2, const float* __restrict__ Wagg,
    const float* __restrict__ g2, const float* __restrict__ b2g,
    const float* __restrict__ m2, const float* __restrict__ v2,
    float* __restrict__ y)
{
    extern __shared__ char sm[];
    int tid  = threadIdx.x;
    int lane = tid & 31;
    int wid  = tid >> 5;
    int b  = blockIdx.z;
    int h0 = blockIdx.y * HCHUNK;
    int w0 = blockIdx.x * 256;

    uint32_t smb = smem_u32(sm);
    float b2v = __ldg(b2);

    int warp_m = wid & 7;
    int warp_n = wid >> 3;
    int pbase  = warp_m * 32;
    int obase  = warp_n * 32;

    const float* xf = x + ((size_t)b * (CIN + 4) + 4) * NPIX;

    // ---- prologue 1: convert Wagg -> fp16 swizzled B tiles (all threads) ----
#pragma unroll 8
    for (int it = 0; it < 72; ++it) {
        int e = tid + 512 * it;          // 0..36863
        int o = e / 576;
        int r = e - o * 576;
        int k = r >> 6, c = r & 63;
        float w = Wagg[e];
        *(__half*)(sm + SM_BW + k * 8192 + SW128((uint32_t)(o * 128 + c * 2))) =
            __float2half_rn(w);
    }

    // ---- prologue 2: fold gate weights, BN2 consts, c4 partials ----
    if (tid < 64) {
        float a = g1[tid] * rsqrtf(v1[tid] + EPSV);
        float wx = W1[tid * 4 + 0] * a, wy = W1[tid * 4 + 1] * a;
        float wz = W1[tid * 4 + 2] * a, ww = W1[tid * 4 + 3] * a;
        float bb = b1[tid] - m1[tid] * a;
        float w2 = W2[tid];
        uint64_t* wp = (uint64_t*)(sm + SM_WP);
        wp[tid * 6 + 0] = pk2(wx, wx);
        wp[tid * 6 + 1] = pk2(wy, wy);
        wp[tid * 6 + 2] = pk2(wz, wz);
        wp[tid * 6 + 3] = pk2(ww, ww);
        wp[tid * 6 + 4] = pk2(bb, bb);
        wp[tid * 6 + 5] = pk2(w2, w2);

        float a2 = g2[tid] * rsqrtf(v2[tid] + EPSV);
        ((float*)(sm + SM_BN))[tid]      = a2;
        ((float*)(sm + SM_BN))[64 + tid] = b2g[tid] - m2[tid] * a2;

        float val = fmaxf(bb, 0.0f) * w2;
#pragma unroll
        for (int o = 16; o > 0; o >>= 1)
            val += __shfl_down_sync(0xffffffffu, val, o);
        if ((tid & 31) == 0) ((float*)(sm + SM_C4))[tid >> 5] = val;
    }
    __syncthreads();

    // ---- prologue 3: gates(h0) by threads 0-255; 3 planes by threads 256-511 ----
    if (tid < 256) {
        compute_gates(sm, (float*)(sm + SM_SG), b, h0, w0, tid, x, mask, b2v);
    } else {
        int t = tid - 256;
        load_plane256(sm, 0, h0 - 1, w0, xf, t);
        load_plane256(sm, 1, h0,     w0, xf, t);
        load_plane256(sm, 2, h0 + 1, w0, xf, t);
    }
    __syncthreads();

    // ---- fragment addressing (hoisted swizzles) ----
    uint32_t aq   = (uint32_t)(pbase + (lane & 15));
    uint32_t acol = (uint32_t)((lane >> 4) * 16);
    uint32_t bg   = (uint32_t)(lane >> 3);
    uint32_t b_n  = (uint32_t)(obase + ((bg >> 1) << 3) + (lane & 7));
    uint32_t b_kb = (bg & 1) * 16;
    int srow = pbase + (lane >> 2);

    uint32_t arow128[3][2], axor[3][2];
#pragma unroll
    for (int q = 0; q < 3; ++q)
#pragma unroll
        for (int mt = 0; mt < 2; ++mt) {
            uint32_t r = aq + (uint32_t)q + (uint32_t)(mt * 16);
            arow128[q][mt] = r * 128;
            axor[q][mt]    = (r & 7) << 4;
        }
    uint32_t boff[2][4];
#pragma unroll
    for (int nt2 = 0; nt2 < 2; ++nt2)
#pragma unroll
        for (int ks = 0; ks < 4; ++ks) {
            uint32_t r = b_n + (uint32_t)(nt2 * 16);
            boff[nt2][ks] = r * 128 + (((uint32_t)(ks * 32) + b_kb) ^ ((r & 7) << 4));
        }

    const float* sc = (const float*)(sm + SM_BN);
    const float* sh = sc + 64;
    int rbase = pbase + (lane >> 2);
    int cbase = obase + (lane & 3) * 2;

    // persistent zero C-quad for ks==0 HMMAs
    float zq[4] = {0.0f, 0.0f, 0.0f, 0.0f};

    for (int i = 0; i < HCHUNK; ++i) {
        int h = h0 + i;

        // ---- overlap work: next-row gates (0-255), next plane (256-511) ----
        if (i < HCHUNK - 1) {
            if (tid < 256) {
                compute_gates(sm, (float*)(sm + SM_SG) + ((i + 1) & 1) * 2304,
                              b, h + 1, w0, tid, x, mask, b2v);
            } else {
                load_plane256(sm, (i + 3) & 3, h + 2, w0, xf, tid - 256);
            }
        }

        const float* sg = (const float*)(sm + SM_SG) + (i & 1) * 2304;

        // packed accumulators: [mt][nt][{(c0,c1),(c2,c3)}]
        uint64_t acc2[2][4][2];
#pragma unroll
        for (int mt = 0; mt < 2; ++mt)
#pragma unroll
            for (int nt = 0; nt < 4; ++nt) {
                acc2[mt][nt][0] = pk2(0.0f, 0.0f);
                acc2[mt][nt][1] = pk2(0.0f, 0.0f);
            }

#pragma unroll
        for (int k = 0; k < 9; ++k) {
            uint32_t pl    = smb + SM_FEAT + (uint32_t)(((i + k / 3) & 3) * PLANE);
            int      qoff  = k % 3;
            uint32_t bbase = smb + SM_BW + (uint32_t)(k * 8192);

            float tmp[2][4][4];

#pragma unroll
            for (int ks = 0; ks < 4; ++ks) {
                uint32_t ah[2][4], bh[2][4];
#pragma unroll
                for (int mt = 0; mt < 2; ++mt) {
                    uint32_t off = arow128[qoff][mt] +
                                   (((uint32_t)(ks * 32) + acol) ^ axor[qoff][mt]);
                    ldsm4(pl + off, ah[mt]);
                }
#pragma unroll
                for (int nt2 = 0; nt2 < 2; ++nt2)
                    ldsm4(bbase + boff[nt2][ks], bh[nt2]);
#pragma unroll
                for (int mt = 0; mt < 2; ++mt)
#pragma unroll
                    for (int nt = 0; nt < 4; ++nt) {
                        const uint32_t* bf = &bh[nt >> 1][(nt & 1) * 2];
                        if (ks == 0) hmma_c(tmp[mt][nt], ah[mt], bf, zq);
                        else         hmma(tmp[mt][nt], ah[mt], bf);
                    }
            }

            // packed fold: (c0,c1) share s_a, (c2,c3) share s_b
#pragma unroll
            for (int mt = 0; mt < 2; ++mt) {
                float s_a = sg[k * 256 + srow + mt * 16];
                float s_b = sg[k * 256 + srow + mt * 16 + 8];
                uint64_t sa2 = pk2(s_a, s_a);
                uint64_t sb2 = pk2(s_b, s_b);
#pragma unroll
                for (int nt = 0; nt < 4; ++nt) {
                    acc2[mt][nt][0] = fma2(pk2(tmp[mt][nt][0], tmp[mt][nt][1]),
                                           sa2, acc2[mt][nt][0]);
                    acc2[mt][nt][1] = fma2(pk2(tmp[mt][nt][2], tmp[mt][nt][3]),
                                           sb2, acc2[mt][nt][1]);
                }
            }
        }

        // ---- epilogue row h ----
        float* yb = y + ((size_t)b * COUT) * NPIX + (size_t)h * WW_ + w0;
#pragma unroll
        for (int mt = 0; mt < 2; ++mt) {
#pragma unroll
            for (int nt = 0; nt < 4; ++nt) {
                int o0 = cbase + nt * 8;
                int r0 = rbase + mt * 16;
                float s0 = sc[o0], h0c = sh[o0];
                float s1 = sc[o0 + 1], h1c = sh[o0 + 1];
                float a0, a1, a2v, a3;
                upk2(acc2[mt][nt][0], a0, a1);
                upk2(acc2[mt][nt][1], a2v, a3);
                yb[(size_t)o0       * NPIX + r0]     = fmaxf(fmaf(a0,  s0, h0c), 0.0f);
                yb[(size_t)(o0 + 1) * NPIX + r0]     = fmaxf(fmaf(a1,  s1, h1c), 0.0f);
                yb[(size_t)o0       * NPIX + r0 + 8] = fmaxf(fmaf(a2v, s0, h0c), 0.0f);
                yb[(size_t)(o0 + 1) * NPIX + r0 + 8] = fmaxf(fmaf(a3,  s1, h1c), 0.0f);
            }
        }

        __syncthreads();
    }
}

// ---------------------------------------------------------------------------
extern "C" void kernel_launch(void* const* d_in, const int* in_sizes, int n_in,
                              void* d_out, int out_size)
{
    const float* x     = (const float*)d_in[0];
    const int*   mask  = (const int*)  d_in[1];
    const float* W1    = (const float*)d_in[2];
    const float* bn1_g = (const float*)d_in[3];
    const float* bn1_b = (const float*)d_in[4];
    const float* bn1_m = (const float*)d_in[5];
    const float* bn1_v = (const float*)d_in[6];
    const float* W2    = (const float*)d_in[7];
    const float* b2    = (const float*)d_in[8];
    const float* Wagg  = (const float*)d_in[9];
    const float* bn2_g = (const float*)d_in[10];
    const float* bn2_b = (const float*)d_in[11];
    const float* bn2_m = (const float*)d_in[12];
    const float* bn2_v = (const float*)d_in[13];
    float* y = (float*)d_out;

    static int smem_set = 0;
    if (!smem_set) {
        cudaFuncSetAttribute(fused_pac, cudaFuncAttributeMaxDynamicSharedMemorySize,
                             SM_TOTAL);
        smem_set = 1;
    }

    dim3 grid(WW_ / 256, HH_ / HCHUNK, BB);
    fused_pac<<<grid, 512, SM_TOTAL>>>(x, mask, W1, bn1_g, bn1_b, bn1_m, bn1_v,
                                       W2, b2, Wagg, bn2_g, bn2_b, bn2_m, bn2_v, y);
}